// round 12
// baseline (speedup 1.0000x reference)
#include <cuda_runtime.h>
#include <cuda_fp16.h>
#include <cstdint>
#include <math.h>

#define TOK 4096
#define DIM 1024
#define HID 1024
#define NE  16
#define SHH 2048

#define BMT 128       // CTA tile M
#define BNT 128       // CTA tile N
#define KC  64        // K chunk (fp16 elements) = 128 bytes
#define TLB 16384     // one operand tile: 128 rows x 128B (swizzled)
#define STG (2 * TLB) // A+B per stage
#define SMEM_G3    (3 * STG + 256)            // 98560: 3-stage -> 2 CTAs/SM
#define SMEM_FUSED (2 * STG + 32768 + 256)    // 2-stage + u-buffer

// k_mix block ranges
#define ND1 512                    // dense<1> tiles: (SHH/BNT)*(TOK/BMT)
#define NT2 2048                   // sW2 transpose tiles: (DIM/32)*(SHH/32)
#define NTW 49152                  // routed transposes: 32*32*48
#define NMIX (ND1 + NT2 + NTW)

// ---------------- scratch ----------------------------------------------------
__device__ int    g_cnt[NE];
__device__ int    g_list[NE * TOK];                 // packed entry: token*2 + slot
__device__ float  g_went[TOK * 2];                  // routing weight per entry
__device__ __half g_embh[(size_t)TOK * DIM];        // fp16 embeddings
__device__ __half g_xh[(size_t)TOK * DIM];          // fp16 x
__device__ float  g_ubuf[(size_t)TOK * 2 * HID];    // expert outputs (f32)
__device__ __half g_hbufh[(size_t)TOK * 2 * HID];   // SwiGLU hidden (fp16)
__device__ __half g_zbufh[(size_t)TOK * SHH];       // shared-expert hidden (fp16)
__device__ __half g_tw1h[(size_t)NE * DIM * HID];   // W1^T  [e][h][d]
__device__ __half g_tw3h[(size_t)NE * DIM * HID];   // W3^T  [e][h][d]
__device__ __half g_tw2h[(size_t)NE * DIM * HID];   // W2^T  [e][d][h]
__device__ __half g_tsw1h[(size_t)SHH * DIM];       // sW1^T [h][d]
__device__ __half g_tsw2h[(size_t)DIM * SHH];       // sW2^T [d][h]

// ---------------- helpers ------------------------------------------------------
__device__ __forceinline__ uint32_t smem_u32(const void* p) {
    uint32_t a;
    asm("{ .reg .u64 t; cvta.to.shared.u64 t, %1; cvt.u32.u64 %0, t; }"
        : "=r"(a) : "l"(p));
    return a;
}
__device__ __forceinline__ uint32_t swz(uint32_t o) {  // XOR bits[4:6] ^= row[0:2]
    return o ^ (((o >> 7) & 7u) << 4);
}
__device__ __forceinline__ void cp16(uint32_t d, const void* s) {
    asm volatile("cp.async.cg.shared.global [%0], [%1], 16;" :: "r"(d), "l"(s));
}
__device__ __forceinline__ void cp16z(uint32_t d, const void* s, uint32_t n) {
    asm volatile("cp.async.cg.shared.global [%0], [%1], 16, %2;" :: "r"(d), "l"(s), "r"(n));
}
__device__ __forceinline__ void cp_commit() { asm volatile("cp.async.commit_group;"); }
__device__ __forceinline__ void cp_wait1()  { asm volatile("cp.async.wait_group 1;"); }
__device__ __forceinline__ void cp_wait0()  { asm volatile("cp.async.wait_group 0;"); }

__device__ __forceinline__ void ldsm4(uint32_t* r, uint32_t a) {
    asm volatile("ldmatrix.sync.aligned.m8n8.x4.shared.b16 {%0,%1,%2,%3}, [%4];"
                 : "=r"(r[0]), "=r"(r[1]), "=r"(r[2]), "=r"(r[3]) : "r"(a));
}
__device__ __forceinline__ void mma16(float* d, const uint32_t* a, uint32_t b0, uint32_t b1) {
    asm volatile("mma.sync.aligned.m16n8k16.row.col.f32.f16.f16.f32 "
                 "{%0,%1,%2,%3}, {%4,%5,%6,%7}, {%8,%9}, {%0,%1,%2,%3};"
                 : "+f"(d[0]), "+f"(d[1]), "+f"(d[2]), "+f"(d[3])
                 : "r"(a[0]), "r"(a[1]), "r"(a[2]), "r"(a[3]), "r"(b0), "r"(b1));
}

struct MMCtx {
    const __half* a_src[4];   // per-thread A row pointers (gathered)
    uint32_t      dst[4];     // swizzled dst offsets (same pattern for A and B)
    uint32_t      a_sz[4];    // 16 or 0 (zero-fill padded rows)
};
// Fully materialized chunk-invariant fragment offsets: one IADD per ldsm.
struct FragOff {
    uint32_t a[8];    // [mi*4 + ks]
    uint32_t b[16];   // [p*4 + ks]
};

__device__ __forceinline__ void mm_setup_dst(MMCtx& cx, int tid) {
    int c8 = tid & 7, rb = tid >> 3;
#pragma unroll
    for (int i = 0; i < 4; i++) {
        int row = rb + 32 * i;
        cx.dst[i] = swz((uint32_t)row * 128u + (uint32_t)c8 * 16u);
    }
}
__device__ __forceinline__ void frag_setup(FragOff& fo, int lane, int wm, int wn) {
    uint32_t lk = (uint32_t)(lane & 16);
#pragma unroll
    for (int mi = 0; mi < 2; mi++) {
        int row = wm * 32 + mi * 16 + (lane & 15);
        uint32_t base = (uint32_t)row * 128u, mask = (uint32_t)(row & 7) << 4;
#pragma unroll
        for (int ks = 0; ks < 4; ks++)
            fo.a[mi * 4 + ks] = base + (((uint32_t)ks * 32u + lk) ^ mask);
    }
#pragma unroll
    for (int p = 0; p < 4; p++) {
        int rowN = wn * 64 + p * 16 + (lane & 15);
        uint32_t base = (uint32_t)rowN * 128u, mask = (uint32_t)(rowN & 7) << 4;
#pragma unroll
        for (int ks = 0; ks < 4; ks++)
            fo.b[p * 4 + ks] = base + (((uint32_t)ks * 32u + lk) ^ mask);
    }
}
__device__ __forceinline__ void mm_issue(const MMCtx& cx, const __half* const* b_src,
                                         uint32_t sb, int buf, int c) {
    uint32_t ab = sb + buf * STG, bb = ab + TLB;
#pragma unroll
    for (int i = 0; i < 4; i++) cp16z(ab + cx.dst[i], cx.a_src[i] + c * KC, cx.a_sz[i]);
#pragma unroll
    for (int i = 0; i < 4; i++) cp16(bb + cx.dst[i], b_src[i] + c * KC);
    cp_commit();
}
__device__ __forceinline__ void mm_compute(uint32_t ab, uint32_t bb, const FragOff& fo,
                                           float acc[2][8][4]) {
#pragma unroll
    for (int ks = 0; ks < 4; ks++) {
        uint32_t a[2][4];
#pragma unroll
        for (int mi = 0; mi < 2; mi++)
            ldsm4(a[mi], ab + fo.a[mi * 4 + ks]);
#pragma unroll
        for (int p = 0; p < 4; p++) {
            uint32_t bf[4];
            ldsm4(bf, bb + fo.b[p * 4 + ks]);
            mma16(acc[0][2*p],   a[0], bf[0], bf[2]);
            mma16(acc[1][2*p],   a[1], bf[0], bf[2]);
            mma16(acc[0][2*p+1], a[0], bf[1], bf[3]);
            mma16(acc[1][2*p+1], a[1], bf[1], bf[3]);
        }
    }
}
// 2-stage, two syncs (for the fused moe13 kernel whose u-buffer forbids stage 3)
__device__ __forceinline__ void mm_loop2(const MMCtx& cx, const __half* const* b_src,
                                         uint32_t sb, int K, const FragOff& fo,
                                         float acc[2][8][4]) {
    int NCH = K / KC;
    mm_issue(cx, b_src, sb, 0, 0);
    for (int c = 0; c < NCH; c++) {
        int b = c & 1;
        if (c + 1 < NCH) { mm_issue(cx, b_src, sb, b ^ 1, c + 1); cp_wait1(); }
        else             { cp_wait0(); }
        __syncthreads();
        mm_compute(sb + b * STG, sb + b * STG + TLB, fo, acc);
        __syncthreads();
    }
}
// 3-stage, ONE sync per chunk
__device__ __forceinline__ void mm_loop3(const MMCtx& cx, const __half* const* b_src,
                                         uint32_t sb, int K, const FragOff& fo,
                                         float acc[2][8][4]) {
    int NCH = K / KC;
    mm_issue(cx, b_src, sb, 0, 0);
    mm_issue(cx, b_src, sb, 1, 1);
    int b = 0, b2 = 2;
    for (int c = 0; c < NCH; c++) {
        if (c == NCH - 1) cp_wait0(); else cp_wait1();
        __syncthreads();
        if (c + 2 < NCH) mm_issue(cx, b_src, sb, b2, c + 2);
        mm_compute(sb + b * STG, sb + b * STG + TLB, fo, acc);
        if (++b == 3) b = 0;
        if (++b2 == 3) b2 = 0;
    }
}

// ---------------- small kernels -------------------------------------------------
__global__ void k_zero() { if (threadIdx.x < NE) g_cnt[threadIdx.x] = 0; }

__global__ void k_half(const float* __restrict__ s, __half* __restrict__ d, int n4) {
    int i = blockIdx.x * blockDim.x + threadIdx.x;
    if (i < n4) {
        float4 v = ((const float4*)s)[i];
        __half2* o = (__half2*)d + i * 2;
        o[0] = __floats2half2_rn(v.x, v.y);
        o[1] = __floats2half2_rn(v.z, v.w);
    }
}

// gate + fp16 conversion of embeddings (row already in registers)
__global__ void k_gate(const float* __restrict__ emb, const float* __restrict__ gw)
{
    int t = (blockIdx.x * blockDim.x + threadIdx.x) >> 5;
    int lane = threadIdx.x & 31;
    if (t >= TOK) return;
    const float* row = emb + (size_t)t * DIM;
    float xr[32];
#pragma unroll
    for (int i = 0; i < 32; i++) xr[i] = row[lane + 32 * i];
    __half* eh = g_embh + (size_t)t * DIM;
#pragma unroll
    for (int i = 0; i < 32; i++) eh[lane + 32 * i] = __float2half_rn(xr[i]);
    float sc[NE];
#pragma unroll
    for (int e = 0; e < NE; e++) {
        const float* g = gw + e * DIM;
        float acc = 0.f;
#pragma unroll
        for (int i = 0; i < 32; i++) acc += xr[i] * g[lane + 32 * i];
#pragma unroll
        for (int o = 16; o > 0; o >>= 1) acc += __shfl_xor_sync(0xffffffffu, acc, o);
        sc[e] = acc;
    }
    if (lane == 0) {
        float m = sc[0];
#pragma unroll
        for (int e = 1; e < NE; e++) m = fmaxf(m, sc[e]);
        float s = 0.f;
#pragma unroll
        for (int e = 0; e < NE; e++) { sc[e] = expf(sc[e] - m); s += sc[e]; }
        float inv = 1.f / s;
        int i0 = 0;
#pragma unroll
        for (int e = 1; e < NE; e++) if (sc[e] > sc[i0]) i0 = e;
        int i1 = (i0 == 0) ? 1 : 0;
#pragma unroll
        for (int e = 0; e < NE; e++) if (e != i0 && sc[e] > sc[i1]) i1 = e;
        int p0 = atomicAdd(&g_cnt[i0], 1);
        g_list[i0 * TOK + p0] = t * 2;
        g_went[t * 2] = sc[i0] * inv;
        int p1 = atomicAdd(&g_cnt[i1], 1);
        g_list[i1 * TOK + p1] = t * 2 + 1;
        g_went[t * 2 + 1] = sc[i1] * inv;
    }
}

// generic transpose for the shared-expert weight sW1
__global__ void k_trh(const float* __restrict__ src, __half* __restrict__ dst, int R, int C)
{
    __shared__ float t[32][33];
    int c0 = blockIdx.x * 32, r0 = blockIdx.y * 32;
    int tx = threadIdx.x, ty = threadIdx.y;
#pragma unroll
    for (int i = 0; i < 32; i += 8)
        t[ty + i][tx] = src[(size_t)(r0 + ty + i) * C + c0 + tx];
    __syncthreads();
#pragma unroll
    for (int i = 0; i < 32; i += 8)
        dst[(size_t)(c0 + ty + i) * R + r0 + tx] = __float2half_rn(t[tx][ty + i]);
}

// ---------------- k_mix: dense<1> GEMM tiles + ALL remaining transposes ----------
// bids [0, ND1): shared-expert GEMM1 tile -> g_zbufh = half(silu(embh@tsw1 + sB1))
// bids [ND1, ND1+NT2): sW2 transpose tile
// bids [ND1+NT2, NMIX): routed weight transpose tile (48 sets of 32x32 grid)
__global__ void __launch_bounds__(256, 2) k_mix(
    const __half* __restrict__ A,       // embh
    const __half* __restrict__ Bt,      // tsw1h
    const float* __restrict__ bias,     // sB1
    const float* __restrict__ sW2, __half* __restrict__ tsw2h,
    const float* __restrict__ W1, __half* __restrict__ T1,
    const float* __restrict__ W3, __half* __restrict__ T3,
    const float* __restrict__ W2, __half* __restrict__ T2)
{
    int bid = blockIdx.x;
    int tid = threadIdx.x;
    __shared__ float t[32][33];

    if (bid < ND1) {
        // ---- dense GEMM1 tile ----
        extern __shared__ char dsm[];
        char* base = (char*)(((uintptr_t)dsm + 127) & ~(uintptr_t)127);
        uint32_t sb = smem_u32(base);
        int lane = tid & 31, w = tid >> 5;
        int wm = w & 3, wn = w >> 2;
        int r0 = (bid >> 4) * BMT, c0 = (bid & 15) * BNT;

        MMCtx cx;
        const __half* bsrc[4];
        mm_setup_dst(cx, tid);
        {
            int c8 = tid & 7, rb = tid >> 3;
#pragma unroll
            for (int i = 0; i < 4; i++) {
                int row = rb + 32 * i;
                cx.a_src[i] = A + (size_t)(r0 + row) * DIM + c8 * 8;
                cx.a_sz[i] = 16;
                bsrc[i] = Bt + (size_t)(c0 + row) * DIM + c8 * 8;
            }
        }
        FragOff fo;
        frag_setup(fo, lane, wm, wn);
        float acc[2][8][4] = {};
        mm_loop3(cx, bsrc, sb, DIM, fo, acc);

        int g = lane >> 2, t4 = lane & 3;
#pragma unroll
        for (int mi = 0; mi < 2; mi++)
#pragma unroll
            for (int h = 0; h < 2; h++) {
                int row = r0 + wm * 32 + mi * 16 + g + h * 8;
#pragma unroll
                for (int nj = 0; nj < 8; nj++) {
                    int col = c0 + wn * 64 + nj * 8 + 2 * t4;
                    float v0 = acc[mi][nj][h * 2 + 0] + bias[col];
                    float v1 = acc[mi][nj][h * 2 + 1] + bias[col + 1];
                    v0 = v0 / (1.f + __expf(-v0));
                    v1 = v1 / (1.f + __expf(-v1));
                    *(__half2*)(g_zbufh + (size_t)row * SHH + col) = __floats2half2_rn(v0, v1);
                }
            }
        return;
    }

    // ---- transpose tile ----
    int tx = tid & 31, ty = tid >> 5;
    const float* src;
    __half* dst;
    int R, C;
    size_t boff = 0;
    int cx_, ry_;
    if (bid < ND1 + NT2) {
        int idx = bid - ND1;
        cx_ = idx & 31; ry_ = idx >> 5;          // DIM/32 x SHH/32
        src = sW2; dst = tsw2h; R = SHH; C = DIM;
    } else {
        int idx = bid - ND1 - NT2;
        cx_ = idx & 31; ry_ = (idx >> 5) & 31;
        int z = idx >> 10;                        // 0..47
        int set = z >> 4, e = z & 15;
        src = (set == 0) ? W1 : (set == 1) ? W3 : W2;
        dst = (set == 0) ? T1 : (set == 1) ? T3 : T2;
        R = DIM; C = HID;
        boff = (size_t)e * DIM * HID;
    }
    int c0 = cx_ * 32, r0 = ry_ * 32;
#pragma unroll
    for (int i = 0; i < 32; i += 8)
        t[ty + i][tx] = src[boff + (size_t)(r0 + ty + i) * C + c0 + tx];
    __syncthreads();
#pragma unroll
    for (int i = 0; i < 32; i += 8)
        dst[boff + (size_t)(c0 + ty + i) * R + r0 + tx] = __float2half_rn(t[tx][ty + i]);
}

// ---------------- dense GEMM2 (shared expert): out = zbufh @ tsw2 + sB2 (f32) ----
__global__ void __launch_bounds__(256, 2) k_dense0(
    const float* __restrict__ bias,
    float* __restrict__ C)
{
    extern __shared__ char dsm[];
    char* base = (char*)(((uintptr_t)dsm + 127) & ~(uintptr_t)127);
    uint32_t sb = smem_u32(base);
    int tid = threadIdx.x, lane = tid & 31, w = tid >> 5;
    int wm = w & 3, wn = w >> 2;
    int r0 = blockIdx.y * BMT, c0 = blockIdx.x * BNT;

    MMCtx cx;
    const __half* bsrc[4];
    mm_setup_dst(cx, tid);
    {
        int c8 = tid & 7, rb = tid >> 3;
#pragma unroll
        for (int i = 0; i < 4; i++) {
            int row = rb + 32 * i;
            cx.a_src[i] = g_zbufh + (size_t)(r0 + row) * SHH + c8 * 8;
            cx.a_sz[i] = 16;
            bsrc[i] = g_tsw2h + (size_t)(c0 + row) * SHH + c8 * 8;
        }
    }
    FragOff fo;
    frag_setup(fo, lane, wm, wn);
    float acc[2][8][4] = {};
    mm_loop3(cx, bsrc, sb, SHH, fo, acc);

    int g = lane >> 2, t4 = lane & 3;
#pragma unroll
    for (int mi = 0; mi < 2; mi++)
#pragma unroll
        for (int h = 0; h < 2; h++) {
            int row = r0 + wm * 32 + mi * 16 + g + h * 8;
#pragma unroll
            for (int nj = 0; nj < 8; nj++) {
                int col = c0 + wn * 64 + nj * 8 + 2 * t4;
                float v0 = acc[mi][nj][h * 2 + 0] + bias[col];
                float v1 = acc[mi][nj][h * 2 + 1] + bias[col + 1];
                *(float2*)(C + (size_t)row * DIM + col) = make_float2(v0, v1);
            }
        }
}

// ---------------- fused routed GEMM1: u = A@W1+b1 (pass1, smem), h = silu(u)*(A@W3+b3)
__global__ void __launch_bounds__(256, 2) k_moe13(
    const __half* __restrict__ xh, const __half* __restrict__ embh,
    const __half* __restrict__ W1t, const __half* __restrict__ W3t,
    const float* __restrict__ b1all, const float* __restrict__ b3all)
{
    int e = blockIdx.z;
    int cnt = g_cnt[e];
    int r0 = blockIdx.y * BMT;
    if (r0 >= cnt) return;
    int c0 = blockIdx.x * BNT;

    extern __shared__ char dsm[];
    __shared__ int rs[BMT];
    char* base = (char*)(((uintptr_t)dsm + 127) & ~(uintptr_t)127);
    uint32_t sb = smem_u32(base);
    uint32_t su = sb + 2 * STG;          // u-buffer: 32 half2 per thread, su[i][tid]
    int tid = threadIdx.x, lane = tid & 31, w = tid >> 5;
    int wm = w & 3, wn = w >> 2;

    if (tid < BMT) rs[tid] = (r0 + tid < cnt) ? g_list[e * TOK + r0 + tid] : -1;
    __syncthreads();

    MMCtx cx;
    const __half* b1src[4];
    const __half* b3src[4];
    mm_setup_dst(cx, tid);
    {
        int c8 = tid & 7, rb = tid >> 3;
        const __half* abase = (e < 2) ? xh : embh;
#pragma unroll
        for (int i = 0; i < 4; i++) {
            int row = rb + 32 * i;
            int ent = rs[row];
            bool v = (ent >= 0);
            cx.a_src[i] = v ? abase + (size_t)(ent >> 1) * DIM + c8 * 8 : abase;
            cx.a_sz[i] = v ? 16 : 0;
            b1src[i] = W1t + ((size_t)e * HID + c0 + row) * DIM + c8 * 8;
            b3src[i] = W3t + ((size_t)e * HID + c0 + row) * DIM + c8 * 8;
        }
    }
    const float* b1 = b1all + (size_t)e * HID;
    const float* b3 = b3all + (size_t)e * HID;
    FragOff fo;
    frag_setup(fo, lane, wm, wn);
    int g = lane >> 2, t4 = lane & 3;

    float acc[2][8][4] = {};
    // ---- pass 1: W1 ----
    mm_loop2(cx, b1src, sb, DIM, fo, acc);
#pragma unroll
    for (int mi = 0; mi < 2; mi++)
#pragma unroll
        for (int h = 0; h < 2; h++)
#pragma unroll
            for (int nj = 0; nj < 8; nj++) {
                int col = c0 + wn * 64 + nj * 8 + 2 * t4;
                float u0 = acc[mi][nj][h * 2 + 0] + b1[col];
                float u1 = acc[mi][nj][h * 2 + 1] + b1[col + 1];
                int i = (mi * 2 + h) * 8 + nj;
                uint32_t ua = su + (uint32_t)i * 1024u + (uint32_t)tid * 4u;
                __half2 hu = __floats2half2_rn(u0, u1);
                asm volatile("st.shared.b32 [%0], %1;" :: "r"(ua), "r"(*(uint32_t*)&hu));
                acc[mi][nj][h * 2 + 0] = 0.f;
                acc[mi][nj][h * 2 + 1] = 0.f;
            }
    __syncthreads();   // stage buffers must be free before pass-2 prefetch

    // ---- pass 2: W3 ----
    mm_loop2(cx, b3src, sb, DIM, fo, acc);
#pragma unroll
    for (int mi = 0; mi < 2; mi++)
#pragma unroll
        for (int h = 0; h < 2; h++) {
            int lr = wm * 32 + mi * 16 + g + h * 8;
            int ent = rs[lr];
            if (ent < 0) continue;
#pragma unroll
            for (int nj = 0; nj < 8; nj++) {
                int col = c0 + wn * 64 + nj * 8 + 2 * t4;
                float v0 = acc[mi][nj][h * 2 + 0] + b3[col];
                float v1 = acc[mi][nj][h * 2 + 1] + b3[col + 1];
                int i = (mi * 2 + h) * 8 + nj;
                uint32_t ua = su + (uint32_t)i * 1024u + (uint32_t)tid * 4u;
                uint32_t ur;
                asm volatile("ld.shared.b32 %0, [%1];" : "=r"(ur) : "r"(ua));
                __half2 hu = *(__half2*)&ur;
                float u0 = __half2float(__low2half(hu));
                float u1 = __half2float(__high2half(hu));
                v0 = (u0 / (1.f + __expf(-u0))) * v0;
                v1 = (u1 / (1.f + __expf(-u1))) * v1;
                *(__half2*)(g_hbufh + (size_t)ent * HID + col) = __floats2half2_rn(v0, v1);
            }
        }
}

// ---------------- routed GEMM2: ubuf[ent] = hbufh[ent] @ W2 + b2 (f32) ------------
__global__ void __launch_bounds__(256, 2) k_moe2(
    const __half* __restrict__ W2t,
    const float* __restrict__ b2all)
{
    int e = blockIdx.z;
    int cnt = g_cnt[e];
    int r0 = blockIdx.y * BMT;
    if (r0 >= cnt) return;
    int c0 = blockIdx.x * BNT;

    extern __shared__ char dsm[];
    __shared__ int rs[BMT];
    char* base = (char*)(((uintptr_t)dsm + 127) & ~(uintptr_t)127);
    uint32_t sb = smem_u32(base);
    int tid = threadIdx.x, lane = tid & 31, w = tid >> 5;
    int wm = w & 3, wn = w >> 2;

    if (tid < BMT) rs[tid] = (r0 + tid < cnt) ? g_list[e * TOK + r0 + tid] : -1;
    __syncthreads();

    MMCtx cx;
    const __half* bsrc[4];
    mm_setup_dst(cx, tid);
    {
        int c8 = tid & 7, rb = tid >> 3;
#pragma unroll
        for (int i = 0; i < 4; i++) {
            int row = rb + 32 * i;
            int ent = rs[row];
            bool v = (ent >= 0);
            cx.a_src[i] = v ? g_hbufh + (size_t)ent * HID + c8 * 8 : g_hbufh;
            cx.a_sz[i] = v ? 16 : 0;
            bsrc[i] = W2t + ((size_t)e * DIM + c0 + row) * HID + c8 * 8;
        }
    }
    FragOff fo;
    frag_setup(fo, lane, wm, wn);
    float acc[2][8][4] = {};
    mm_loop3(cx, bsrc, sb, HID, fo, acc);

    const float* bias = b2all + (size_t)e * DIM;
    int g = lane >> 2, t4 = lane & 3;
#pragma unroll
    for (int mi = 0; mi < 2; mi++)
#pragma unroll
        for (int h = 0; h < 2; h++) {
            int lr = wm * 32 + mi * 16 + g + h * 8;
            int ent = rs[lr];
            if (ent < 0) continue;
#pragma unroll
            for (int nj = 0; nj < 8; nj++) {
                int col = c0 + wn * 64 + nj * 8 + 2 * t4;
                float v0 = acc[mi][nj][h * 2 + 0] + bias[col];
                float v1 = acc[mi][nj][h * 2 + 1] + bias[col + 1];
                *(float2*)(g_ubuf + (size_t)ent * DIM + col) = make_float2(v0, v1);
            }
        }
}

// ---------------- final combine: out[t] += w0*o[2t] + w1*o[2t+1] ------------------
__global__ void k_comb(float* __restrict__ out) {
    int t = blockIdx.x;
    int d = threadIdx.x * 4;
    float w0 = g_went[t * 2], w1 = g_went[t * 2 + 1];
    float4 a = *(const float4*)(g_ubuf + (size_t)(t * 2) * DIM + d);
    float4 b = *(const float4*)(g_ubuf + (size_t)(t * 2 + 1) * DIM + d);
    float4 z = *(float4*)(out + (size_t)t * DIM + d);
    z.x += w0 * a.x + w1 * b.x;
    z.y += w0 * a.y + w1 * b.y;
    z.z += w0 * a.z + w1 * b.z;
    z.w += w0 * a.w + w1 * b.w;
    *(float4*)(out + (size_t)t * DIM + d) = z;
}

// ---------------- launcher ---------------------------------------------------------
extern "C" void kernel_launch(void* const* d_in, const int* in_sizes, int n_in,
                              void* d_out, int out_size)
{
    const float* emb = (const float*)d_in[0];
    const float* x   = (const float*)d_in[1];
    const float* gw  = (const float*)d_in[2];
    const float* W1  = (const float*)d_in[3];
    const float* B1  = (const float*)d_in[4];
    const float* W2  = (const float*)d_in[5];
    const float* B2  = (const float*)d_in[6];
    const float* W3  = (const float*)d_in[7];
    const float* B3  = (const float*)d_in[8];
    const float* sW1 = (const float*)d_in[9];
    const float* sB1 = (const float*)d_in[10];
    const float* sW2 = (const float*)d_in[11];
    const float* sB2 = (const float*)d_in[12];
    float* out = (float*)d_out;

    cudaFuncSetAttribute(k_mix,    cudaFuncAttributeMaxDynamicSharedMemorySize, SMEM_G3);
    cudaFuncSetAttribute(k_dense0, cudaFuncAttributeMaxDynamicSharedMemorySize, SMEM_G3);
    cudaFuncSetAttribute(k_moe13,  cudaFuncAttributeMaxDynamicSharedMemorySize, SMEM_FUSED);
    cudaFuncSetAttribute(k_moe2,   cudaFuncAttributeMaxDynamicSharedMemorySize, SMEM_G3);

    __half *embh, *xh, *tw1h, *tw3h, *tw2h, *tsw1h, *tsw2h;
    cudaGetSymbolAddress((void**)&embh,  g_embh);
    cudaGetSymbolAddress((void**)&xh,    g_xh);
    cudaGetSymbolAddress((void**)&tw1h,  g_tw1h);
    cudaGetSymbolAddress((void**)&tw3h,  g_tw3h);
    cudaGetSymbolAddress((void**)&tw2h,  g_tw2h);
    cudaGetSymbolAddress((void**)&tsw1h, g_tsw1h);
    cudaGetSymbolAddress((void**)&tsw2h, g_tsw2h);

    dim3 tb(32, 8);
    int n4a = TOK * DIM / 4;

    // Launch order arranged so 0-based launch #3 is k_mix (the profiled one).
    k_zero<<<1, 32>>>();                                              // 0
    k_trh<<<dim3(SHH / 32, DIM / 32), tb>>>(sW1, tsw1h, DIM, SHH);    // 1
    k_gate<<<TOK / 4, 128>>>(emb, gw);                                // 2 (emits embh)
    k_mix<<<NMIX, 256, SMEM_G3>>>(embh, tsw1h, sB1,                   // 3 (profiled)
                                  sW2, tsw2h, W1, tw1h, W3, tw3h, W2, tw2h);

    k_half<<<(n4a + 255) / 256, 256>>>(x, xh, n4a);
    k_dense0<<<dim3(DIM / BNT, TOK / BMT), 256, SMEM_G3>>>(sB2, out);

    // routed experts (fused W1+W3, then W2)
    k_moe13<<<dim3(HID / BNT, TOK / BMT, NE), 256, SMEM_FUSED>>>(xh, embh, tw1h, tw3h, B1, B3);
    k_moe2 <<<dim3(DIM / BNT, TOK / BMT, NE), 256, SMEM_G3>>>(tw2h, B2);
    k_comb<<<TOK, 256>>>(out);

    (void)in_sizes; (void)n_in; (void)out_size;
}

// round 13
// speedup vs baseline: 1.0349x; 1.0349x over previous
#include <cuda_runtime.h>
#include <cuda_fp16.h>
#include <cstdint>
#include <math.h>

#define TOK 4096
#define DIM 1024
#define HID 1024
#define NE  16
#define SHH 2048

#define BMT 128       // CTA tile M
#define BNT 128       // CTA tile N
#define KC  64        // K chunk (fp16 elements) = 128 bytes
#define TLB 16384     // one operand tile: 128 rows x 128B (swizzled)
#define STG (2 * TLB) // A+B per stage
#define SMEM_G3    (3 * STG + 256)            // 98560: 3-stage -> 2 CTAs/SM
#define SMEM_FUSED (2 * STG + 32768 + 256)    // 2-stage + u-buffer

// k_mix work decomposition
#define ND1 512                    // dense<1> GEMM tiles
#define NT2 2048                   // sW2 transpose tiles (32 x 64)
#define NTR 49152                  // routed weight transpose tiles (32*32*48)
#define NXH 1024                   // x->fp16 chunks (1024 float4 each)
#define TOTW (NT2 + NTR + NXH)     // 52224 work items
#define TPW 32                     // items per worker block
#define NWK (TOTW / TPW)           // 1632 worker blocks
#define NMIX (ND1 + NWK)           // 2144

// ---------------- scratch ----------------------------------------------------
__device__ int    g_cnt[NE];
__device__ int    g_list[NE * TOK];                 // packed entry: token*2 + slot
__device__ float  g_went[TOK * 2];                  // routing weight per entry
__device__ __half g_embh[(size_t)TOK * DIM];        // fp16 embeddings
__device__ __half g_xh[(size_t)TOK * DIM];          // fp16 x
__device__ float  g_ubuf[(size_t)TOK * 2 * HID];    // expert outputs (f32)
__device__ __half g_hbufh[(size_t)TOK * 2 * HID];   // SwiGLU hidden (fp16)
__device__ __half g_zbufh[(size_t)TOK * SHH];       // shared-expert hidden (fp16)
__device__ __half g_tw1h[(size_t)NE * DIM * HID];   // W1^T  [e][h][d]
__device__ __half g_tw3h[(size_t)NE * DIM * HID];   // W3^T  [e][h][d]
__device__ __half g_tw2h[(size_t)NE * DIM * HID];   // W2^T  [e][d][h]
__device__ __half g_tsw1h[(size_t)SHH * DIM];       // sW1^T [h][d]
__device__ __half g_tsw2h[(size_t)DIM * SHH];       // sW2^T [d][h]

// ---------------- helpers ------------------------------------------------------
__device__ __forceinline__ uint32_t smem_u32(const void* p) {
    uint32_t a;
    asm("{ .reg .u64 t; cvta.to.shared.u64 t, %1; cvt.u32.u64 %0, t; }"
        : "=r"(a) : "l"(p));
    return a;
}
__device__ __forceinline__ uint32_t swz(uint32_t o) {  // XOR bits[4:6] ^= row[0:2]
    return o ^ (((o >> 7) & 7u) << 4);
}
__device__ __forceinline__ void cp16(uint32_t d, const void* s) {
    asm volatile("cp.async.cg.shared.global [%0], [%1], 16;" :: "r"(d), "l"(s));
}
__device__ __forceinline__ void cp16z(uint32_t d, const void* s, uint32_t n) {
    asm volatile("cp.async.cg.shared.global [%0], [%1], 16, %2;" :: "r"(d), "l"(s), "r"(n));
}
__device__ __forceinline__ void cp_commit() { asm volatile("cp.async.commit_group;"); }
__device__ __forceinline__ void cp_wait1()  { asm volatile("cp.async.wait_group 1;"); }
__device__ __forceinline__ void cp_wait0()  { asm volatile("cp.async.wait_group 0;"); }

__device__ __forceinline__ void ldsm4(uint32_t* r, uint32_t a) {
    asm volatile("ldmatrix.sync.aligned.m8n8.x4.shared.b16 {%0,%1,%2,%3}, [%4];"
                 : "=r"(r[0]), "=r"(r[1]), "=r"(r[2]), "=r"(r[3]) : "r"(a));
}
__device__ __forceinline__ void mma16(float* d, const uint32_t* a, uint32_t b0, uint32_t b1) {
    asm volatile("mma.sync.aligned.m16n8k16.row.col.f32.f16.f16.f32 "
                 "{%0,%1,%2,%3}, {%4,%5,%6,%7}, {%8,%9}, {%0,%1,%2,%3};"
                 : "+f"(d[0]), "+f"(d[1]), "+f"(d[2]), "+f"(d[3])
                 : "r"(a[0]), "r"(a[1]), "r"(a[2]), "r"(a[3]), "r"(b0), "r"(b1));
}

struct MMCtx {
    const __half* a_src[4];
    uint32_t      dst[4];
    uint32_t      a_sz[4];
};
struct FragOff {
    uint32_t a[8];    // [mi*4 + ks]
    uint32_t b[16];   // [p*4 + ks]
};

__device__ __forceinline__ void mm_setup_dst(MMCtx& cx, int tid) {
    int c8 = tid & 7, rb = tid >> 3;
#pragma unroll
    for (int i = 0; i < 4; i++) {
        int row = rb + 32 * i;
        cx.dst[i] = swz((uint32_t)row * 128u + (uint32_t)c8 * 16u);
    }
}
__device__ __forceinline__ void frag_setup(FragOff& fo, int lane, int wm, int wn) {
    uint32_t lk = (uint32_t)(lane & 16);
#pragma unroll
    for (int mi = 0; mi < 2; mi++) {
        int row = wm * 32 + mi * 16 + (lane & 15);
        uint32_t base = (uint32_t)row * 128u, mask = (uint32_t)(row & 7) << 4;
#pragma unroll
        for (int ks = 0; ks < 4; ks++)
            fo.a[mi * 4 + ks] = base + (((uint32_t)ks * 32u + lk) ^ mask);
    }
#pragma unroll
    for (int p = 0; p < 4; p++) {
        int rowN = wn * 64 + p * 16 + (lane & 15);
        uint32_t base = (uint32_t)rowN * 128u, mask = (uint32_t)(rowN & 7) << 4;
#pragma unroll
        for (int ks = 0; ks < 4; ks++)
            fo.b[p * 4 + ks] = base + (((uint32_t)ks * 32u + lk) ^ mask);
    }
}
__device__ __forceinline__ void mm_issue(const MMCtx& cx, const __half* const* b_src,
                                         uint32_t sb, int buf, int c) {
    uint32_t ab = sb + buf * STG, bb = ab + TLB;
#pragma unroll
    for (int i = 0; i < 4; i++) cp16z(ab + cx.dst[i], cx.a_src[i] + c * KC, cx.a_sz[i]);
#pragma unroll
    for (int i = 0; i < 4; i++) cp16(bb + cx.dst[i], b_src[i] + c * KC);
    cp_commit();
}
__device__ __forceinline__ void mm_compute(uint32_t ab, uint32_t bb, const FragOff& fo,
                                           float acc[2][8][4]) {
#pragma unroll
    for (int ks = 0; ks < 4; ks++) {
        uint32_t a[2][4];
#pragma unroll
        for (int mi = 0; mi < 2; mi++)
            ldsm4(a[mi], ab + fo.a[mi * 4 + ks]);
#pragma unroll
        for (int p = 0; p < 4; p++) {
            uint32_t bf[4];
            ldsm4(bf, bb + fo.b[p * 4 + ks]);
            mma16(acc[0][2*p],   a[0], bf[0], bf[2]);
            mma16(acc[1][2*p],   a[1], bf[0], bf[2]);
            mma16(acc[0][2*p+1], a[0], bf[1], bf[3]);
            mma16(acc[1][2*p+1], a[1], bf[1], bf[3]);
        }
    }
}
// 2-stage, two syncs (fused moe13: u-buffer forbids stage 3)
__device__ __forceinline__ void mm_loop2(const MMCtx& cx, const __half* const* b_src,
                                         uint32_t sb, int K, const FragOff& fo,
                                         float acc[2][8][4]) {
    int NCH = K / KC;
    mm_issue(cx, b_src, sb, 0, 0);
    for (int c = 0; c < NCH; c++) {
        int b = c & 1;
        if (c + 1 < NCH) { mm_issue(cx, b_src, sb, b ^ 1, c + 1); cp_wait1(); }
        else             { cp_wait0(); }
        __syncthreads();
        mm_compute(sb + b * STG, sb + b * STG + TLB, fo, acc);
        __syncthreads();
    }
}
// 3-stage, ONE sync per chunk
__device__ __forceinline__ void mm_loop3(const MMCtx& cx, const __half* const* b_src,
                                         uint32_t sb, int K, const FragOff& fo,
                                         float acc[2][8][4]) {
    int NCH = K / KC;
    mm_issue(cx, b_src, sb, 0, 0);
    mm_issue(cx, b_src, sb, 1, 1);
    int b = 0, b2 = 2;
    for (int c = 0; c < NCH; c++) {
        if (c == NCH - 1) cp_wait0(); else cp_wait1();
        __syncthreads();
        if (c + 2 < NCH) mm_issue(cx, b_src, sb, b2, c + 2);
        mm_compute(sb + b * STG, sb + b * STG + TLB, fo, acc);
        if (++b == 3) b = 0;
        if (++b2 == 3) b2 = 0;
    }
}

// ---------------- small kernels -------------------------------------------------
__global__ void k_zero() { if (threadIdx.x < NE) g_cnt[threadIdx.x] = 0; }

// gate + fp16 conversion of embeddings (row already in registers)
__global__ void k_gate(const float* __restrict__ emb, const float* __restrict__ gw)
{
    int t = (blockIdx.x * blockDim.x + threadIdx.x) >> 5;
    int lane = threadIdx.x & 31;
    if (t >= TOK) return;
    const float* row = emb + (size_t)t * DIM;
    float xr[32];
#pragma unroll
    for (int i = 0; i < 32; i++) xr[i] = row[lane + 32 * i];
    __half* eh = g_embh + (size_t)t * DIM;
#pragma unroll
    for (int i = 0; i < 32; i++) eh[lane + 32 * i] = __float2half_rn(xr[i]);
    float sc[NE];
#pragma unroll
    for (int e = 0; e < NE; e++) {
        const float* g = gw + e * DIM;
        float acc = 0.f;
#pragma unroll
        for (int i = 0; i < 32; i++) acc += xr[i] * g[lane + 32 * i];
#pragma unroll
        for (int o = 16; o > 0; o >>= 1) acc += __shfl_xor_sync(0xffffffffu, acc, o);
        sc[e] = acc;
    }
    if (lane == 0) {
        float m = sc[0];
#pragma unroll
        for (int e = 1; e < NE; e++) m = fmaxf(m, sc[e]);
        float s = 0.f;
#pragma unroll
        for (int e = 0; e < NE; e++) { sc[e] = expf(sc[e] - m); s += sc[e]; }
        float inv = 1.f / s;
        int i0 = 0;
#pragma unroll
        for (int e = 1; e < NE; e++) if (sc[e] > sc[i0]) i0 = e;
        int i1 = (i0 == 0) ? 1 : 0;
#pragma unroll
        for (int e = 0; e < NE; e++) if (e != i0 && sc[e] > sc[i1]) i1 = e;
        int p0 = atomicAdd(&g_cnt[i0], 1);
        g_list[i0 * TOK + p0] = t * 2;
        g_went[t * 2] = sc[i0] * inv;
        int p1 = atomicAdd(&g_cnt[i1], 1);
        g_list[i1 * TOK + p1] = t * 2 + 1;
        g_went[t * 2 + 1] = sc[i1] * inv;
    }
}

// generic transpose (used for sW1 only)
__global__ void k_trh(const float* __restrict__ src, __half* __restrict__ dst, int R, int C)
{
    __shared__ float t[32][33];
    int c0 = blockIdx.x * 32, r0 = blockIdx.y * 32;
    int tx = threadIdx.x, ty = threadIdx.y;
#pragma unroll
    for (int i = 0; i < 32; i += 8)
        t[ty + i][tx] = src[(size_t)(r0 + ty + i) * C + c0 + tx];
    __syncthreads();
#pragma unroll
    for (int i = 0; i < 32; i += 8)
        dst[(size_t)(c0 + ty + i) * R + r0 + tx] = __float2half_rn(t[tx][ty + i]);
}

// ---------------- k_mix: dense<1> GEMM tiles + coarse transpose/convert workers --
// bids [0, ND1): shared-expert GEMM1 tile -> g_zbufh = half(silu(embh@tsw1 + sB1))
// bids [ND1, NMIX): worker block, TPW work items each:
//   item < NT2:        sW2 transpose tile
//   item < NT2+NTR:    routed weight transpose tile
//   else:              x->fp16 chunk (1024 float4)
__global__ void __launch_bounds__(256, 2) k_mix(
    const __half* __restrict__ A,       // embh
    const __half* __restrict__ Bt,      // tsw1h
    const float* __restrict__ bias,     // sB1
    const float* __restrict__ sW2, __half* __restrict__ tsw2h,
    const float* __restrict__ W1, __half* __restrict__ T1,
    const float* __restrict__ W3, __half* __restrict__ T3,
    const float* __restrict__ W2, __half* __restrict__ T2,
    const float* __restrict__ x, __half* __restrict__ xh)
{
    int bid = blockIdx.x;
    int tid = threadIdx.x;
    __shared__ float t[32][33];

    if (bid < ND1) {
        // ---- dense GEMM1 tile ----
        extern __shared__ char dsm[];
        char* base = (char*)(((uintptr_t)dsm + 127) & ~(uintptr_t)127);
        uint32_t sb = smem_u32(base);
        int lane = tid & 31, w = tid >> 5;
        int wm = w & 3, wn = w >> 2;
        int r0 = (bid >> 4) * BMT, c0 = (bid & 15) * BNT;

        MMCtx cx;
        const __half* bsrc[4];
        mm_setup_dst(cx, tid);
        {
            int c8 = tid & 7, rb = tid >> 3;
#pragma unroll
            for (int i = 0; i < 4; i++) {
                int row = rb + 32 * i;
                cx.a_src[i] = A + (size_t)(r0 + row) * DIM + c8 * 8;
                cx.a_sz[i] = 16;
                bsrc[i] = Bt + (size_t)(c0 + row) * DIM + c8 * 8;
            }
        }
        FragOff fo;
        frag_setup(fo, lane, wm, wn);
        float acc[2][8][4] = {};
        mm_loop3(cx, bsrc, sb, DIM, fo, acc);

        int g = lane >> 2, t4 = lane & 3;
#pragma unroll
        for (int mi = 0; mi < 2; mi++)
#pragma unroll
            for (int h = 0; h < 2; h++) {
                int row = r0 + wm * 32 + mi * 16 + g + h * 8;
#pragma unroll
                for (int nj = 0; nj < 8; nj++) {
                    int col = c0 + wn * 64 + nj * 8 + 2 * t4;
                    float v0 = acc[mi][nj][h * 2 + 0] + bias[col];
                    float v1 = acc[mi][nj][h * 2 + 1] + bias[col + 1];
                    v0 = v0 / (1.f + __expf(-v0));
                    v1 = v1 / (1.f + __expf(-v1));
                    *(__half2*)(g_zbufh + (size_t)row * SHH + col) = __floats2half2_rn(v0, v1);
                }
            }
        return;
    }

    // ---- worker block: TPW items ----
    int tx = tid & 31, ty = tid >> 5;
    int wbase = (bid - ND1) * TPW;
    for (int it = 0; it < TPW; it++) {
        int idx = wbase + it;
        if (idx < NT2 + NTR) {
            const float* src;
            __half* dst;
            int R, C;
            size_t boff = 0;
            int cx_, ry_;
            if (idx < NT2) {
                cx_ = idx & 31; ry_ = idx >> 5;   // DIM/32 x SHH/32
                src = sW2; dst = tsw2h; R = SHH; C = DIM;
            } else {
                int j = idx - NT2;
                cx_ = j & 31; ry_ = (j >> 5) & 31;
                int z = j >> 10;                   // 0..47
                int set = z >> 4, e = z & 15;
                src = (set == 0) ? W1 : (set == 1) ? W3 : W2;
                dst = (set == 0) ? T1 : (set == 1) ? T3 : T2;
                R = DIM; C = HID;
                boff = (size_t)e * DIM * HID;
            }
            int c0 = cx_ * 32, r0 = ry_ * 32;
#pragma unroll
            for (int i = 0; i < 32; i += 8)
                t[ty + i][tx] = src[boff + (size_t)(r0 + ty + i) * C + c0 + tx];
            __syncthreads();
#pragma unroll
            for (int i = 0; i < 32; i += 8)
                dst[boff + (size_t)(c0 + ty + i) * R + r0 + tx] = __float2half_rn(t[tx][ty + i]);
            __syncthreads();
        } else {
            int rest = idx - (NT2 + NTR);          // [0, NXH)
            int base = rest * 1024 + tid;
#pragma unroll
            for (int j = 0; j < 4; j++) {
                int i = base + j * 256;
                float4 v = ((const float4*)x)[i];
                __half2* o = (__half2*)xh + (size_t)i * 2;
                o[0] = __floats2half2_rn(v.x, v.y);
                o[1] = __floats2half2_rn(v.z, v.w);
            }
        }
    }
}

// ---------------- dense GEMM2 (shared expert): out = zbufh @ tsw2 + sB2 (f32) ----
__global__ void __launch_bounds__(256, 2) k_dense0(
    const float* __restrict__ bias,
    float* __restrict__ C)
{
    extern __shared__ char dsm[];
    char* base = (char*)(((uintptr_t)dsm + 127) & ~(uintptr_t)127);
    uint32_t sb = smem_u32(base);
    int tid = threadIdx.x, lane = tid & 31, w = tid >> 5;
    int wm = w & 3, wn = w >> 2;
    int r0 = blockIdx.y * BMT, c0 = blockIdx.x * BNT;

    MMCtx cx;
    const __half* bsrc[4];
    mm_setup_dst(cx, tid);
    {
        int c8 = tid & 7, rb = tid >> 3;
#pragma unroll
        for (int i = 0; i < 4; i++) {
            int row = rb + 32 * i;
            cx.a_src[i] = g_zbufh + (size_t)(r0 + row) * SHH + c8 * 8;
            cx.a_sz[i] = 16;
            bsrc[i] = g_tsw2h + (size_t)(c0 + row) * SHH + c8 * 8;
        }
    }
    FragOff fo;
    frag_setup(fo, lane, wm, wn);
    float acc[2][8][4] = {};
    mm_loop3(cx, bsrc, sb, SHH, fo, acc);

    int g = lane >> 2, t4 = lane & 3;
#pragma unroll
    for (int mi = 0; mi < 2; mi++)
#pragma unroll
        for (int h = 0; h < 2; h++) {
            int row = r0 + wm * 32 + mi * 16 + g + h * 8;
#pragma unroll
            for (int nj = 0; nj < 8; nj++) {
                int col = c0 + wn * 64 + nj * 8 + 2 * t4;
                float v0 = acc[mi][nj][h * 2 + 0] + bias[col];
                float v1 = acc[mi][nj][h * 2 + 1] + bias[col + 1];
                *(float2*)(C + (size_t)row * DIM + col) = make_float2(v0, v1);
            }
        }
}

// ---------------- fused routed GEMM1: u = A@W1+b1 (pass1, smem), h = silu(u)*(A@W3+b3)
__global__ void __launch_bounds__(256, 2) k_moe13(
    const __half* __restrict__ xh, const __half* __restrict__ embh,
    const __half* __restrict__ W1t, const __half* __restrict__ W3t,
    const float* __restrict__ b1all, const float* __restrict__ b3all)
{
    int e = blockIdx.z;
    int cnt = g_cnt[e];
    int r0 = blockIdx.y * BMT;
    if (r0 >= cnt) return;
    int c0 = blockIdx.x * BNT;

    extern __shared__ char dsm[];
    __shared__ int rs[BMT];
    char* base = (char*)(((uintptr_t)dsm + 127) & ~(uintptr_t)127);
    uint32_t sb = smem_u32(base);
    uint32_t su = sb + 2 * STG;          // u-buffer: 32 half2 per thread, su[i][tid]
    int tid = threadIdx.x, lane = tid & 31, w = tid >> 5;
    int wm = w & 3, wn = w >> 2;

    if (tid < BMT) rs[tid] = (r0 + tid < cnt) ? g_list[e * TOK + r0 + tid] : -1;
    __syncthreads();

    MMCtx cx;
    const __half* b1src[4];
    const __half* b3src[4];
    mm_setup_dst(cx, tid);
    {
        int c8 = tid & 7, rb = tid >> 3;
        const __half* abase = (e < 2) ? xh : embh;
#pragma unroll
        for (int i = 0; i < 4; i++) {
            int row = rb + 32 * i;
            int ent = rs[row];
            bool v = (ent >= 0);
            cx.a_src[i] = v ? abase + (size_t)(ent >> 1) * DIM + c8 * 8 : abase;
            cx.a_sz[i] = v ? 16 : 0;
            b1src[i] = W1t + ((size_t)e * HID + c0 + row) * DIM + c8 * 8;
            b3src[i] = W3t + ((size_t)e * HID + c0 + row) * DIM + c8 * 8;
        }
    }
    const float* b1 = b1all + (size_t)e * HID;
    const float* b3 = b3all + (size_t)e * HID;
    FragOff fo;
    frag_setup(fo, lane, wm, wn);
    int g = lane >> 2, t4 = lane & 3;

    float acc[2][8][4] = {};
    // ---- pass 1: W1 ----
    mm_loop2(cx, b1src, sb, DIM, fo, acc);
#pragma unroll
    for (int mi = 0; mi < 2; mi++)
#pragma unroll
        for (int h = 0; h < 2; h++)
#pragma unroll
            for (int nj = 0; nj < 8; nj++) {
                int col = c0 + wn * 64 + nj * 8 + 2 * t4;
                float u0 = acc[mi][nj][h * 2 + 0] + b1[col];
                float u1 = acc[mi][nj][h * 2 + 1] + b1[col + 1];
                int i = (mi * 2 + h) * 8 + nj;
                uint32_t ua = su + (uint32_t)i * 1024u + (uint32_t)tid * 4u;
                __half2 hu = __floats2half2_rn(u0, u1);
                asm volatile("st.shared.b32 [%0], %1;" :: "r"(ua), "r"(*(uint32_t*)&hu));
                acc[mi][nj][h * 2 + 0] = 0.f;
                acc[mi][nj][h * 2 + 1] = 0.f;
            }
    __syncthreads();   // stage buffers must be free before pass-2 prefetch

    // ---- pass 2: W3 ----
    mm_loop2(cx, b3src, sb, DIM, fo, acc);
#pragma unroll
    for (int mi = 0; mi < 2; mi++)
#pragma unroll
        for (int h = 0; h < 2; h++) {
            int lr = wm * 32 + mi * 16 + g + h * 8;
            int ent = rs[lr];
            if (ent < 0) continue;
#pragma unroll
            for (int nj = 0; nj < 8; nj++) {
                int col = c0 + wn * 64 + nj * 8 + 2 * t4;
                float v0 = acc[mi][nj][h * 2 + 0] + b3[col];
                float v1 = acc[mi][nj][h * 2 + 1] + b3[col + 1];
                int i = (mi * 2 + h) * 8 + nj;
                uint32_t ua = su + (uint32_t)i * 1024u + (uint32_t)tid * 4u;
                uint32_t ur;
                asm volatile("ld.shared.b32 %0, [%1];" : "=r"(ur) : "r"(ua));
                __half2 hu = *(__half2*)&ur;
                float u0 = __half2float(__low2half(hu));
                float u1 = __half2float(__high2half(hu));
                v0 = (u0 / (1.f + __expf(-u0))) * v0;
                v1 = (u1 / (1.f + __expf(-u1))) * v1;
                *(__half2*)(g_hbufh + (size_t)ent * HID + col) = __floats2half2_rn(v0, v1);
            }
        }
}

// ---------------- routed GEMM2: ubuf[ent] = hbufh[ent] @ W2 + b2 (f32) ------------
__global__ void __launch_bounds__(256, 2) k_moe2(
    const __half* __restrict__ W2t,
    const float* __restrict__ b2all)
{
    int e = blockIdx.z;
    int cnt = g_cnt[e];
    int r0 = blockIdx.y * BMT;
    if (r0 >= cnt) return;
    int c0 = blockIdx.x * BNT;

    extern __shared__ char dsm[];
    __shared__ int rs[BMT];
    char* base = (char*)(((uintptr_t)dsm + 127) & ~(uintptr_t)127);
    uint32_t sb = smem_u32(base);
    int tid = threadIdx.x, lane = tid & 31, w = tid >> 5;
    int wm = w & 3, wn = w >> 2;

    if (tid < BMT) rs[tid] = (r0 + tid < cnt) ? g_list[e * TOK + r0 + tid] : -1;
    __syncthreads();

    MMCtx cx;
    const __half* bsrc[4];
    mm_setup_dst(cx, tid);
    {
        int c8 = tid & 7, rb = tid >> 3;
#pragma unroll
        for (int i = 0; i < 4; i++) {
            int row = rb + 32 * i;
            int ent = rs[row];
            bool v = (ent >= 0);
            cx.a_src[i] = v ? g_hbufh + (size_t)ent * HID + c8 * 8 : g_hbufh;
            cx.a_sz[i] = v ? 16 : 0;
            bsrc[i] = W2t + ((size_t)e * DIM + c0 + row) * HID + c8 * 8;
        }
    }
    FragOff fo;
    frag_setup(fo, lane, wm, wn);
    float acc[2][8][4] = {};
    mm_loop3(cx, bsrc, sb, HID, fo, acc);

    const float* bias = b2all + (size_t)e * DIM;
    int g = lane >> 2, t4 = lane & 3;
#pragma unroll
    for (int mi = 0; mi < 2; mi++)
#pragma unroll
        for (int h = 0; h < 2; h++) {
            int lr = wm * 32 + mi * 16 + g + h * 8;
            int ent = rs[lr];
            if (ent < 0) continue;
#pragma unroll
            for (int nj = 0; nj < 8; nj++) {
                int col = c0 + wn * 64 + nj * 8 + 2 * t4;
                float v0 = acc[mi][nj][h * 2 + 0] + bias[col];
                float v1 = acc[mi][nj][h * 2 + 1] + bias[col + 1];
                *(float2*)(g_ubuf + (size_t)ent * DIM + col) = make_float2(v0, v1);
            }
        }
}

// ---------------- final combine: out[t] += w0*o[2t] + w1*o[2t+1] ------------------
__global__ void k_comb(float* __restrict__ out) {
    int t = blockIdx.x;
    int d = threadIdx.x * 4;
    float w0 = g_went[t * 2], w1 = g_went[t * 2 + 1];
    float4 a = *(const float4*)(g_ubuf + (size_t)(t * 2) * DIM + d);
    float4 b = *(const float4*)(g_ubuf + (size_t)(t * 2 + 1) * DIM + d);
    float4 z = *(float4*)(out + (size_t)t * DIM + d);
    z.x += w0 * a.x + w1 * b.x;
    z.y += w0 * a.y + w1 * b.y;
    z.z += w0 * a.z + w1 * b.z;
    z.w += w0 * a.w + w1 * b.w;
    *(float4*)(out + (size_t)t * DIM + d) = z;
}

// ---------------- launcher ---------------------------------------------------------
extern "C" void kernel_launch(void* const* d_in, const int* in_sizes, int n_in,
                              void* d_out, int out_size)
{
    const float* emb = (const float*)d_in[0];
    const float* x   = (const float*)d_in[1];
    const float* gw  = (const float*)d_in[2];
    const float* W1  = (const float*)d_in[3];
    const float* B1  = (const float*)d_in[4];
    const float* W2  = (const float*)d_in[5];
    const float* B2  = (const float*)d_in[6];
    const float* W3  = (const float*)d_in[7];
    const float* B3  = (const float*)d_in[8];
    const float* sW1 = (const float*)d_in[9];
    const float* sB1 = (const float*)d_in[10];
    const float* sW2 = (const float*)d_in[11];
    const float* sB2 = (const float*)d_in[12];
    float* out = (float*)d_out;

    cudaFuncSetAttribute(k_mix,    cudaFuncAttributeMaxDynamicSharedMemorySize, SMEM_G3);
    cudaFuncSetAttribute(k_dense0, cudaFuncAttributeMaxDynamicSharedMemorySize, SMEM_G3);
    cudaFuncSetAttribute(k_moe13,  cudaFuncAttributeMaxDynamicSharedMemorySize, SMEM_FUSED);
    cudaFuncSetAttribute(k_moe2,   cudaFuncAttributeMaxDynamicSharedMemorySize, SMEM_G3);

    __half *embh, *xh, *tw1h, *tw3h, *tw2h, *tsw1h, *tsw2h;
    cudaGetSymbolAddress((void**)&embh,  g_embh);
    cudaGetSymbolAddress((void**)&xh,    g_xh);
    cudaGetSymbolAddress((void**)&tw1h,  g_tw1h);
    cudaGetSymbolAddress((void**)&tw3h,  g_tw3h);
    cudaGetSymbolAddress((void**)&tw2h,  g_tw2h);
    cudaGetSymbolAddress((void**)&tsw1h, g_tsw1h);
    cudaGetSymbolAddress((void**)&tsw2h, g_tsw2h);

    dim3 tb(32, 8);

    // Launch order arranged so 0-based launch #3 is k_mix (the profiled one).
    k_zero<<<1, 32>>>();                                              // 0
    k_trh<<<dim3(SHH / 32, DIM / 32), tb>>>(sW1, tsw1h, DIM, SHH);    // 1
    k_gate<<<TOK / 4, 128>>>(emb, gw);                                // 2 (emits embh)
    k_mix<<<NMIX, 256, SMEM_G3>>>(embh, tsw1h, sB1,                   // 3 (profiled)
                                  sW2, tsw2h, W1, tw1h, W3, tw3h, W2, tw2h,
                                  x, xh);

    k_dense0<<<dim3(DIM / BNT, TOK / BMT), 256, SMEM_G3>>>(sB2, out);

    // routed experts (fused W1+W3, then W2)
    k_moe13<<<dim3(HID / BNT, TOK / BMT, NE), 256, SMEM_FUSED>>>(xh, embh, tw1h, tw3h, B1, B3);
    k_moe2 <<<dim3(DIM / BNT, TOK / BMT, NE), 256, SMEM_G3>>>(tw2h, B2);
    k_comb<<<TOK, 256>>>(out);

    (void)in_sizes; (void)n_in; (void)out_size;
}

// round 16
// speedup vs baseline: 1.3128x; 1.2685x over previous
#include <cuda_runtime.h>
#include <cuda_fp16.h>
#include <cstdint>
#include <math.h>

#define TOK 4096
#define DIM 1024
#define HID 1024
#define NE  16
#define SHH 2048

#define BMT 128
#define BNT 128
#define KC  64
#define TLB 16384
#define STG (2 * TLB)
#define SMEM_G3    (3 * STG + 256)
#define SMEM_FUSED (2 * STG + 32768 + 256)

// ---------------- scratch ----------------------------------------------------
__device__ int    g_cnt[NE];
__device__ int    g_list[NE * TOK];
__device__ float  g_went[TOK * 2];
__device__ __half g_embh[(size_t)TOK * DIM];
__device__ __half g_xh[(size_t)TOK * DIM];
__device__ float  g_ubuf[(size_t)TOK * 2 * HID];
__device__ __half g_hbufh[(size_t)TOK * 2 * HID];
__device__ __half g_zbufh[(size_t)TOK * SHH];
__device__ __half g_tw1h[(size_t)NE * DIM * HID];
__device__ __half g_tw3h[(size_t)NE * DIM * HID];
__device__ __half g_tw2h[(size_t)NE * DIM * HID];
__device__ __half g_tsw1h[(size_t)SHH * DIM];
__device__ __half g_tsw2h[(size_t)DIM * SHH];

// ---------------- helpers ------------------------------------------------------
__device__ __forceinline__ uint32_t smem_u32(const void* p) {
    uint32_t a;
    asm("{ .reg .u64 t; cvta.to.shared.u64 t, %1; cvt.u32.u64 %0, t; }"
        : "=r"(a) : "l"(p));
    return a;
}
__device__ __forceinline__ uint32_t swz(uint32_t o) {
    return o ^ (((o >> 7) & 7u) << 4);
}
__device__ __forceinline__ void cp16(uint32_t d, const void* s) {
    asm volatile("cp.async.cg.shared.global [%0], [%1], 16;" :: "r"(d), "l"(s));
}
__device__ __forceinline__ void cp16z(uint32_t d, const void* s, uint32_t n) {
    asm volatile("cp.async.cg.shared.global [%0], [%1], 16, %2;" :: "r"(d), "l"(s), "r"(n));
}
__device__ __forceinline__ void cp_commit() { asm volatile("cp.async.commit_group;"); }
__device__ __forceinline__ void cp_wait1()  { asm volatile("cp.async.wait_group 1;"); }
__device__ __forceinline__ void cp_wait0()  { asm volatile("cp.async.wait_group 0;"); }

__device__ __forceinline__ void ldsm4(uint32_t* r, uint32_t a) {
    asm volatile("ldmatrix.sync.aligned.m8n8.x4.shared.b16 {%0,%1,%2,%3}, [%4];"
                 : "=r"(r[0]), "=r"(r[1]), "=r"(r[2]), "=r"(r[3]) : "r"(a));
}
__device__ __forceinline__ void mma16(float* d, const uint32_t* a, uint32_t b0, uint32_t b1) {
    asm volatile("mma.sync.aligned.m16n8k16.row.col.f32.f16.f16.f32 "
                 "{%0,%1,%2,%3}, {%4,%5,%6,%7}, {%8,%9}, {%0,%1,%2,%3};"
                 : "+f"(d[0]), "+f"(d[1]), "+f"(d[2]), "+f"(d[3])
                 : "r"(a[0]), "r"(a[1]), "r"(a[2]), "r"(a[3]), "r"(b0), "r"(b1));
}

struct MMCtx {
    const __half* a_src[4];
    uint32_t      dst[4];
    uint32_t      a_sz[4];
};
struct FragOff {
    uint32_t a[8];
    uint32_t b[16];
};

__device__ __forceinline__ void mm_setup_dst(MMCtx& cx, int tid) {
    int c8 = tid & 7, rb = tid >> 3;
#pragma unroll
    for (int i = 0; i < 4; i++) {
        int row = rb + 32 * i;
        cx.dst[i] = swz((uint32_t)row * 128u + (uint32_t)c8 * 16u);
    }
}
__device__ __forceinline__ void frag_setup(FragOff& fo, int lane, int wm, int wn) {
    uint32_t lk = (uint32_t)(lane & 16);
#pragma unroll
    for (int mi = 0; mi < 2; mi++) {
        int row = wm * 32 + mi * 16 + (lane & 15);
        uint32_t base = (uint32_t)row * 128u, mask = (uint32_t)(row & 7) << 4;
#pragma unroll
        for (int ks = 0; ks < 4; ks++)
            fo.a[mi * 4 + ks] = base + (((uint32_t)ks * 32u + lk) ^ mask);
    }
#pragma unroll
    for (int p = 0; p < 4; p++) {
        int rowN = wn * 64 + p * 16 + (lane & 15);
        uint32_t base = (uint32_t)rowN * 128u, mask = (uint32_t)(rowN & 7) << 4;
#pragma unroll
        for (int ks = 0; ks < 4; ks++)
            fo.b[p * 4 + ks] = base + (((uint32_t)ks * 32u + lk) ^ mask);
    }
}
__device__ __forceinline__ void mm_issue(const MMCtx& cx, const __half* const* b_src,
                                         uint32_t sb, int buf, int c) {
    uint32_t ab = sb + buf * STG, bb = ab + TLB;
#pragma unroll
    for (int i = 0; i < 4; i++) cp16z(ab + cx.dst[i], cx.a_src[i] + c * KC, cx.a_sz[i]);
#pragma unroll
    for (int i = 0; i < 4; i++) cp16(bb + cx.dst[i], b_src[i] + c * KC);
    cp_commit();
}
__device__ __forceinline__ void mm_compute(uint32_t ab, uint32_t bb, const FragOff& fo,
                                           float acc[2][8][4]) {
#pragma unroll
    for (int ks = 0; ks < 4; ks++) {
        uint32_t a[2][4];
#pragma unroll
        for (int mi = 0; mi < 2; mi++)
            ldsm4(a[mi], ab + fo.a[mi * 4 + ks]);
#pragma unroll
        for (int p = 0; p < 4; p++) {
            uint32_t bf[4];
            ldsm4(bf, bb + fo.b[p * 4 + ks]);
            mma16(acc[0][2*p],   a[0], bf[0], bf[2]);
            mma16(acc[1][2*p],   a[1], bf[0], bf[2]);
            mma16(acc[0][2*p+1], a[0], bf[1], bf[3]);
            mma16(acc[1][2*p+1], a[1], bf[1], bf[3]);
        }
    }
}
__device__ __forceinline__ void mm_loop2(const MMCtx& cx, const __half* const* b_src,
                                         uint32_t sb, int K, const FragOff& fo,
                                         float acc[2][8][4]) {
    int NCH = K / KC;
    mm_issue(cx, b_src, sb, 0, 0);
    for (int c = 0; c < NCH; c++) {
        int b = c & 1;
        if (c + 1 < NCH) { mm_issue(cx, b_src, sb, b ^ 1, c + 1); cp_wait1(); }
        else             { cp_wait0(); }
        __syncthreads();
        mm_compute(sb + b * STG, sb + b * STG + TLB, fo, acc);
        __syncthreads();
    }
}
__device__ __forceinline__ void mm_loop3(const MMCtx& cx, const __half* const* b_src,
                                         uint32_t sb, int K, const FragOff& fo,
                                         float acc[2][8][4]) {
    int NCH = K / KC;
    mm_issue(cx, b_src, sb, 0, 0);
    mm_issue(cx, b_src, sb, 1, 1);
    int b = 0, b2 = 2;
    for (int c = 0; c < NCH; c++) {
        if (c == NCH - 1) cp_wait0(); else cp_wait1();
        __syncthreads();
        if (c + 2 < NCH) mm_issue(cx, b_src, sb, b2, c + 2);
        mm_compute(sb + b * STG, sb + b * STG + TLB, fo, acc);
        if (++b == 3) b = 0;
        if (++b2 == 3) b2 = 0;
    }
}

// ---------------- small kernels -------------------------------------------------
__global__ void k_zero() { if (threadIdx.x < NE) g_cnt[threadIdx.x] = 0; }

__global__ void k_half(const float* __restrict__ s, __half* __restrict__ d, int n4) {
    int i = blockIdx.x * blockDim.x + threadIdx.x;
    if (i < n4) {
        float4 v = ((const float4*)s)[i];
        __half2* o = (__half2*)d + i * 2;
        o[0] = __floats2half2_rn(v.x, v.y);
        o[1] = __floats2half2_rn(v.z, v.w);
    }
}

__global__ void k_gate(const float* __restrict__ emb, const float* __restrict__ gw)
{
    int t = (blockIdx.x * blockDim.x + threadIdx.x) >> 5;
    int lane = threadIdx.x & 31;
    if (t >= TOK) return;
    const float* row = emb + (size_t)t * DIM;
    float xr[32];
#pragma unroll
    for (int i = 0; i < 32; i++) xr[i] = row[lane + 32 * i];
    __half* eh = g_embh + (size_t)t * DIM;
#pragma unroll
    for (int i = 0; i < 32; i++) eh[lane + 32 * i] = __float2half_rn(xr[i]);
    float sc[NE];
#pragma unroll
    for (int e = 0; e < NE; e++) {
        const float* g = gw + e * DIM;
        float acc = 0.f;
#pragma unroll
        for (int i = 0; i < 32; i++) acc += xr[i] * g[lane + 32 * i];
#pragma unroll
        for (int o = 16; o > 0; o >>= 1) acc += __shfl_xor_sync(0xffffffffu, acc, o);
        sc[e] = acc;
    }
    if (lane == 0) {
        float m = sc[0];
#pragma unroll
        for (int e = 1; e < NE; e++) m = fmaxf(m, sc[e]);
        float s = 0.f;
#pragma unroll
        for (int e = 0; e < NE; e++) { sc[e] = expf(sc[e] - m); s += sc[e]; }
        float inv = 1.f / s;
        int i0 = 0;
#pragma unroll
        for (int e = 1; e < NE; e++) if (sc[e] > sc[i0]) i0 = e;
        int i1 = (i0 == 0) ? 1 : 0;
#pragma unroll
        for (int e = 0; e < NE; e++) if (e != i0 && sc[e] > sc[i1]) i1 = e;
        int p0 = atomicAdd(&g_cnt[i0], 1);
        g_list[i0 * TOK + p0] = t * 2;
        g_went[t * 2] = sc[i0] * inv;
        int p1 = atomicAdd(&g_cnt[i1], 1);
        g_list[i1 * TOK + p1] = t * 2 + 1;
        g_went[t * 2 + 1] = sc[i1] * inv;
    }
}

__global__ void k_trh(const float* __restrict__ src, __half* __restrict__ dst, int R, int C)
{
    __shared__ float t[32][33];
    int c0 = blockIdx.x * 32, r0 = blockIdx.y * 32;
    int tx = threadIdx.x, ty = threadIdx.y;
#pragma unroll
    for (int i = 0; i < 32; i += 8)
        t[ty + i][tx] = src[(size_t)(r0 + ty + i) * C + c0 + tx];
    __syncthreads();
#pragma unroll
    for (int i = 0; i < 32; i += 8)
        dst[(size_t)(c0 + ty + i) * R + r0 + tx] = __float2half_rn(t[tx][ty + i]);
}
__global__ void k_trw(const float* __restrict__ W1, __half* __restrict__ T1,
                      const float* __restrict__ W3, __half* __restrict__ T3,
                      const float* __restrict__ W2, __half* __restrict__ T2)
{
    __shared__ float t[32][33];
    int set = blockIdx.z >> 4, e = blockIdx.z & 15;
    const float* src = (set == 0) ? W1 : (set == 1) ? W3 : W2;
    __half*      dst = (set == 0) ? T1 : (set == 1) ? T3 : T2;
    size_t boff = (size_t)e * DIM * HID;
    int c0 = blockIdx.x * 32, r0 = blockIdx.y * 32;
    int tx = threadIdx.x, ty = threadIdx.y;
#pragma unroll
    for (int i = 0; i < 32; i += 8)
        t[ty + i][tx] = src[boff + (size_t)(r0 + ty + i) * HID + c0 + tx];
    __syncthreads();
#pragma unroll
    for (int i = 0; i < 32; i += 8)
        dst[boff + (size_t)(c0 + ty + i) * DIM + r0 + tx] = __float2half_rn(t[tx][ty + i]);
}

// ---------------- dense GEMM (shared expert) ------------------------------------
// EPI 0: C = acc + bias (f32)   EPI 1: g_zbufh = half(silu(acc + bias))
template<int EPI>
__global__ void __launch_bounds__(256, 2) k_dense(
    const __half* __restrict__ A, int lda,
    const __half* __restrict__ Bt, int K,
    const float* __restrict__ bias,
    float* __restrict__ C, int ldc)
{
    extern __shared__ char dsm[];
    char* base = (char*)(((uintptr_t)dsm + 127) & ~(uintptr_t)127);
    uint32_t sb = smem_u32(base);
    int tid = threadIdx.x, lane = tid & 31, w = tid >> 5;
    int wm = w & 3, wn = w >> 2;
    int r0 = blockIdx.y * BMT, c0 = blockIdx.x * BNT;

    MMCtx cx;
    const __half* bsrc[4];
    mm_setup_dst(cx, tid);
    {
        int c8 = tid & 7, rb = tid >> 3;
#pragma unroll
        for (int i = 0; i < 4; i++) {
            int row = rb + 32 * i;
            cx.a_src[i] = A + (size_t)(r0 + row) * lda + c8 * 8;
            cx.a_sz[i] = 16;
            bsrc[i] = Bt + (size_t)(c0 + row) * K + c8 * 8;
        }
    }
    FragOff fo;
    frag_setup(fo, lane, wm, wn);
    float acc[2][8][4] = {};
    mm_loop3(cx, bsrc, sb, K, fo, acc);

    int g = lane >> 2, t4 = lane & 3;
#pragma unroll
    for (int mi = 0; mi < 2; mi++)
#pragma unroll
        for (int h = 0; h < 2; h++) {
            int row = r0 + wm * 32 + mi * 16 + g + h * 8;
#pragma unroll
            for (int nj = 0; nj < 8; nj++) {
                int col = c0 + wn * 64 + nj * 8 + 2 * t4;
                float v0 = acc[mi][nj][h * 2 + 0] + bias[col];
                float v1 = acc[mi][nj][h * 2 + 1] + bias[col + 1];
                if (EPI == 1) {
                    v0 = v0 / (1.f + __expf(-v0));
                    v1 = v1 / (1.f + __expf(-v1));
                    *(__half2*)(g_zbufh + (size_t)row * SHH + col) = __floats2half2_rn(v0, v1);
                } else {
                    *(float2*)(C + (size_t)row * ldc + col) = make_float2(v0, v1);
                }
            }
        }
}

// ---------------- fused routed GEMM1: u = A@W1+b1 (pass1, smem), h = silu(u)*(A@W3+b3)
__global__ void __launch_bounds__(256, 2) k_moe13(
    const __half* __restrict__ xh, const __half* __restrict__ embh,
    const __half* __restrict__ W1t, const __half* __restrict__ W3t,
    const float* __restrict__ b1all, const float* __restrict__ b3all)
{
    int e = blockIdx.z;
    int cnt = g_cnt[e];
    int r0 = blockIdx.y * BMT;
    if (r0 >= cnt) return;
    int c0 = blockIdx.x * BNT;

    extern __shared__ char dsm[];
    __shared__ int rs[BMT];
    char* base = (char*)(((uintptr_t)dsm + 127) & ~(uintptr_t)127);
    uint32_t sb = smem_u32(base);
    uint32_t su = sb + 2 * STG;
    int tid = threadIdx.x, lane = tid & 31, w = tid >> 5;
    int wm = w & 3, wn = w >> 2;

    if (tid < BMT) rs[tid] = (r0 + tid < cnt) ? g_list[e * TOK + r0 + tid] : -1;
    __syncthreads();

    MMCtx cx;
    const __half* b1src[4];
    const __half* b3src[4];
    mm_setup_dst(cx, tid);
    {
        int c8 = tid & 7, rb = tid >> 3;
        const __half* abase = (e < 2) ? xh : embh;
#pragma unroll
        for (int i = 0; i < 4; i++) {
            int row = rb + 32 * i;
            int ent = rs[row];
            bool v = (ent >= 0);
            cx.a_src[i] = v ? abase + (size_t)(ent >> 1) * DIM + c8 * 8 : abase;
            cx.a_sz[i] = v ? 16 : 0;
            b1src[i] = W1t + ((size_t)e * HID + c0 + row) * DIM + c8 * 8;
            b3src[i] = W3t + ((size_t)e * HID + c0 + row) * DIM + c8 * 8;
        }
    }
    const float* b1 = b1all + (size_t)e * HID;
    const float* b3 = b3all + (size_t)e * HID;
    FragOff fo;
    frag_setup(fo, lane, wm, wn);
    int g = lane >> 2, t4 = lane & 3;

    float acc[2][8][4] = {};
    mm_loop2(cx, b1src, sb, DIM, fo, acc);
#pragma unroll
    for (int mi = 0; mi < 2; mi++)
#pragma unroll
        for (int h = 0; h < 2; h++)
#pragma unroll
            for (int nj = 0; nj < 8; nj++) {
                int col = c0 + wn * 64 + nj * 8 + 2 * t4;
                float u0 = acc[mi][nj][h * 2 + 0] + b1[col];
                float u1 = acc[mi][nj][h * 2 + 1] + b1[col + 1];
                int i = (mi * 2 + h) * 8 + nj;
                uint32_t ua = su + (uint32_t)i * 1024u + (uint32_t)tid * 4u;
                __half2 hu = __floats2half2_rn(u0, u1);
                asm volatile("st.shared.b32 [%0], %1;" :: "r"(ua), "r"(*(uint32_t*)&hu));
                acc[mi][nj][h * 2 + 0] = 0.f;
                acc[mi][nj][h * 2 + 1] = 0.f;
            }
    __syncthreads();

    mm_loop2(cx, b3src, sb, DIM, fo, acc);
#pragma unroll
    for (int mi = 0; mi < 2; mi++)
#pragma unroll
        for (int h = 0; h < 2; h++) {
            int lr = wm * 32 + mi * 16 + g + h * 8;
            int ent = rs[lr];
            if (ent < 0) continue;
#pragma unroll
            for (int nj = 0; nj < 8; nj++) {
                int col = c0 + wn * 64 + nj * 8 + 2 * t4;
                float v0 = acc[mi][nj][h * 2 + 0] + b3[col];
                float v1 = acc[mi][nj][h * 2 + 1] + b3[col + 1];
                int i = (mi * 2 + h) * 8 + nj;
                uint32_t ua = su + (uint32_t)i * 1024u + (uint32_t)tid * 4u;
                uint32_t ur;
                asm volatile("ld.shared.b32 %0, [%1];" : "=r"(ur) : "r"(ua));
                __half2 hu = *(__half2*)&ur;
                float u0 = __half2float(__low2half(hu));
                float u1 = __half2float(__high2half(hu));
                v0 = (u0 / (1.f + __expf(-u0))) * v0;
                v1 = (u1 / (1.f + __expf(-u1))) * v1;
                *(__half2*)(g_hbufh + (size_t)ent * HID + col) = __floats2half2_rn(v0, v1);
            }
        }
}

// ---------------- routed GEMM2: ubuf[ent] = hbufh[ent] @ W2 + b2 (f32) ------------
__global__ void __launch_bounds__(256, 2) k_moe2(
    const __half* __restrict__ W2t,
    const float* __restrict__ b2all)
{
    int e = blockIdx.z;
    int cnt = g_cnt[e];
    int r0 = blockIdx.y * BMT;
    if (r0 >= cnt) return;
    int c0 = blockIdx.x * BNT;

    extern __shared__ char dsm[];
    __shared__ int rs[BMT];
    char* base = (char*)(((uintptr_t)dsm + 127) & ~(uintptr_t)127);
    uint32_t sb = smem_u32(base);
    int tid = threadIdx.x, lane = tid & 31, w = tid >> 5;
    int wm = w & 3, wn = w >> 2;

    if (tid < BMT) rs[tid] = (r0 + tid < cnt) ? g_list[e * TOK + r0 + tid] : -1;
    __syncthreads();

    MMCtx cx;
    const __half* bsrc[4];
    mm_setup_dst(cx, tid);
    {
        int c8 = tid & 7, rb = tid >> 3;
#pragma unroll
        for (int i = 0; i < 4; i++) {
            int row = rb + 32 * i;
            int ent = rs[row];
            bool v = (ent >= 0);
            cx.a_src[i] = v ? g_hbufh + (size_t)ent * HID + c8 * 8 : g_hbufh;
            cx.a_sz[i] = v ? 16 : 0;
            bsrc[i] = W2t + ((size_t)e * DIM + c0 + row) * HID + c8 * 8;
        }
    }
    FragOff fo;
    frag_setup(fo, lane, wm, wn);
    float acc[2][8][4] = {};
    mm_loop3(cx, bsrc, sb, HID, fo, acc);

    const float* bias = b2all + (size_t)e * DIM;
    int g = lane >> 2, t4 = lane & 3;
#pragma unroll
    for (int mi = 0; mi < 2; mi++)
#pragma unroll
        for (int h = 0; h < 2; h++) {
            int lr = wm * 32 + mi * 16 + g + h * 8;
            int ent = rs[lr];
            if (ent < 0) continue;
#pragma unroll
            for (int nj = 0; nj < 8; nj++) {
                int col = c0 + wn * 64 + nj * 8 + 2 * t4;
                float v0 = acc[mi][nj][h * 2 + 0] + bias[col];
                float v1 = acc[mi][nj][h * 2 + 1] + bias[col + 1];
                *(float2*)(g_ubuf + (size_t)ent * DIM + col) = make_float2(v0, v1);
            }
        }
}

// ---------------- final combine: out[t] += w0*o[2t] + w1*o[2t+1] ------------------
__global__ void k_comb(float* __restrict__ out) {
    int t = blockIdx.x;
    int d = threadIdx.x * 4;
    float w0 = g_went[t * 2], w1 = g_went[t * 2 + 1];
    float4 a = *(const float4*)(g_ubuf + (size_t)(t * 2) * DIM + d);
    float4 b = *(const float4*)(g_ubuf + (size_t)(t * 2 + 1) * DIM + d);
    float4 z = *(float4*)(out + (size_t)t * DIM + d);
    z.x += w0 * a.x + w1 * b.x;
    z.y += w0 * a.y + w1 * b.y;
    z.z += w0 * a.z + w1 * b.z;
    z.w += w0 * a.w + w1 * b.w;
    *(float4*)(out + (size_t)t * DIM + d) = z;
}

// ---------------- launcher ---------------------------------------------------------
extern "C" void kernel_launch(void* const* d_in, const int* in_sizes, int n_in,
                              void* d_out, int out_size)
{
    const float* emb = (const float*)d_in[0];
    const float* x   = (const float*)d_in[1];
    const float* gw  = (const float*)d_in[2];
    const float* W1  = (const float*)d_in[3];
    const float* B1  = (const float*)d_in[4];
    const float* W2  = (const float*)d_in[5];
    const float* B2  = (const float*)d_in[6];
    const float* W3  = (const float*)d_in[7];
    const float* B3  = (const float*)d_in[8];
    const float* sW1 = (const float*)d_in[9];
    const float* sB1 = (const float*)d_in[10];
    const float* sW2 = (const float*)d_in[11];
    const float* sB2 = (const float*)d_in[12];
    float* out = (float*)d_out;

    static cudaStream_t s_aux = nullptr;
    static cudaEvent_t  s_evA = nullptr, s_evB = nullptr;
    if (!s_aux) {
        cudaStreamCreateWithFlags(&s_aux, cudaStreamNonBlocking);
        cudaEventCreateWithFlags(&s_evA, cudaEventDisableTiming);
        cudaEventCreateWithFlags(&s_evB, cudaEventDisableTiming);
    }

    cudaFuncSetAttribute(k_dense<0>, cudaFuncAttributeMaxDynamicSharedMemorySize, SMEM_G3);
    cudaFuncSetAttribute(k_dense<1>, cudaFuncAttributeMaxDynamicSharedMemorySize, SMEM_G3);
    cudaFuncSetAttribute(k_moe13,    cudaFuncAttributeMaxDynamicSharedMemorySize, SMEM_FUSED);
    cudaFuncSetAttribute(k_moe2,     cudaFuncAttributeMaxDynamicSharedMemorySize, SMEM_G3);

    __half *embh, *xh, *zbufh, *tw1h, *tw3h, *tw2h, *tsw1h, *tsw2h;
    cudaGetSymbolAddress((void**)&embh,  g_embh);
    cudaGetSymbolAddress((void**)&xh,    g_xh);
    cudaGetSymbolAddress((void**)&zbufh, g_zbufh);
    cudaGetSymbolAddress((void**)&tw1h,  g_tw1h);
    cudaGetSymbolAddress((void**)&tw3h,  g_tw3h);
    cudaGetSymbolAddress((void**)&tw2h,  g_tw2h);
    cudaGetSymbolAddress((void**)&tsw1h, g_tsw1h);
    cudaGetSymbolAddress((void**)&tsw2h, g_tsw2h);

    dim3 tb(32, 8);
    int n4a = TOK * DIM / 4;

    // stream 0: zero, then fork
    k_zero<<<1, 32>>>();
    cudaEventRecord(s_evA, 0);

    // aux stream: DRAM-bound prep overlapping with gate + dense<1> on stream 0
    cudaStreamWaitEvent(s_aux, s_evA, 0);
    k_half<<<(n4a + 255) / 256, 256, 0, s_aux>>>(x, xh, n4a);
    k_trh <<<dim3(DIM / 32, SHH / 32), tb, 0, s_aux>>>(sW2, tsw2h, SHH, DIM);
    k_trw <<<dim3(HID / 32, DIM / 32, 3 * NE), tb, 0, s_aux>>>(W1, tw1h, W3, tw3h, W2, tw2h);
    cudaEventRecord(s_evB, s_aux);

    // stream 0 main branch (tensor-bound)
    k_trh<<<dim3(SHH / 32, DIM / 32), tb>>>(sW1, tsw1h, DIM, SHH);
    k_gate<<<TOK / 4, 128>>>(emb, gw);
    k_dense<1><<<dim3(SHH / BNT, TOK / BMT), 256, SMEM_G3>>>(embh, DIM, tsw1h, DIM, sB1, out, SHH);

    // join
    cudaStreamWaitEvent(0, s_evB, 0);

    k_dense<0><<<dim3(DIM / BNT, TOK / BMT), 256, SMEM_G3>>>(zbufh, SHH, tsw2h, SHH, sB2, out, DIM);
    k_moe13<<<dim3(HID / BNT, TOK / BMT, NE), 256, SMEM_FUSED>>>(xh, embh, tw1h, tw3h, B1, B3);
    k_moe2 <<<dim3(DIM / BNT, TOK / BMT, NE), 256, SMEM_G3>>>(tw2h, B2);
    k_comb<<<TOK, 256>>>(out);

    (void)in_sizes; (void)n_in; (void)out_size;
}

// round 17
// speedup vs baseline: 1.4025x; 1.0684x over previous
#include <cuda_runtime.h>
#include <cuda_fp16.h>
#include <cstdint>
#include <math.h>

#define TOK 4096
#define DIM 1024
#define HID 1024
#define NE  16
#define SHH 2048

#define BMT 128
#define BNT 128
#define KC  64
#define TLB 16384
#define STG (2 * TLB)
#define SMEM_G3    (3 * STG + 256)
#define SMEM_FUSED (2 * STG + 32768 + 256)

// ---------------- scratch ----------------------------------------------------
__device__ int    g_cnt[NE];
__device__ int    g_list[NE * TOK];
__device__ float  g_went[TOK * 2];
__device__ __half g_embh[(size_t)TOK * DIM];
__device__ __half g_xh[(size_t)TOK * DIM];
__device__ float  g_ubuf[(size_t)TOK * 2 * HID];
__device__ __half g_hbufh[(size_t)TOK * 2 * HID];
__device__ __half g_zbufh[(size_t)TOK * SHH];
__device__ __half g_tw1h[(size_t)NE * DIM * HID];
__device__ __half g_tw3h[(size_t)NE * DIM * HID];
__device__ __half g_tw2h[(size_t)NE * DIM * HID];
__device__ __half g_tsw1h[(size_t)SHH * DIM];
__device__ __half g_tsw2h[(size_t)DIM * SHH];

// ---------------- helpers ------------------------------------------------------
__device__ __forceinline__ uint32_t smem_u32(const void* p) {
    uint32_t a;
    asm("{ .reg .u64 t; cvta.to.shared.u64 t, %1; cvt.u32.u64 %0, t; }"
        : "=r"(a) : "l"(p));
    return a;
}
__device__ __forceinline__ uint32_t swz(uint32_t o) {
    return o ^ (((o >> 7) & 7u) << 4);
}
__device__ __forceinline__ void cp16(uint32_t d, const void* s) {
    asm volatile("cp.async.cg.shared.global [%0], [%1], 16;" :: "r"(d), "l"(s));
}
__device__ __forceinline__ void cp16z(uint32_t d, const void* s, uint32_t n) {
    asm volatile("cp.async.cg.shared.global [%0], [%1], 16, %2;" :: "r"(d), "l"(s), "r"(n));
}
__device__ __forceinline__ void cp_commit() { asm volatile("cp.async.commit_group;"); }
__device__ __forceinline__ void cp_wait1()  { asm volatile("cp.async.wait_group 1;"); }
__device__ __forceinline__ void cp_wait0()  { asm volatile("cp.async.wait_group 0;"); }

__device__ __forceinline__ void ldsm4(uint32_t* r, uint32_t a) {
    asm volatile("ldmatrix.sync.aligned.m8n8.x4.shared.b16 {%0,%1,%2,%3}, [%4];"
                 : "=r"(r[0]), "=r"(r[1]), "=r"(r[2]), "=r"(r[3]) : "r"(a));
}
__device__ __forceinline__ void mma16(float* d, const uint32_t* a, uint32_t b0, uint32_t b1) {
    asm volatile("mma.sync.aligned.m16n8k16.row.col.f32.f16.f16.f32 "
                 "{%0,%1,%2,%3}, {%4,%5,%6,%7}, {%8,%9}, {%0,%1,%2,%3};"
                 : "+f"(d[0]), "+f"(d[1]), "+f"(d[2]), "+f"(d[3])
                 : "r"(a[0]), "r"(a[1]), "r"(a[2]), "r"(a[3]), "r"(b0), "r"(b1));
}

struct MMCtx {
    const __half* a_src[4];
    uint32_t      dst[4];
    uint32_t      a_sz[4];
};
struct FragOff {
    uint32_t a[8];
    uint32_t b[16];
};

__device__ __forceinline__ void mm_setup_dst(MMCtx& cx, int tid) {
    int c8 = tid & 7, rb = tid >> 3;
#pragma unroll
    for (int i = 0; i < 4; i++) {
        int row = rb + 32 * i;
        cx.dst[i] = swz((uint32_t)row * 128u + (uint32_t)c8 * 16u);
    }
}
__device__ __forceinline__ void frag_setup(FragOff& fo, int lane, int wm, int wn) {
    uint32_t lk = (uint32_t)(lane & 16);
#pragma unroll
    for (int mi = 0; mi < 2; mi++) {
        int row = wm * 32 + mi * 16 + (lane & 15);
        uint32_t base = (uint32_t)row * 128u, mask = (uint32_t)(row & 7) << 4;
#pragma unroll
        for (int ks = 0; ks < 4; ks++)
            fo.a[mi * 4 + ks] = base + (((uint32_t)ks * 32u + lk) ^ mask);
    }
#pragma unroll
    for (int p = 0; p < 4; p++) {
        int rowN = wn * 64 + p * 16 + (lane & 15);
        uint32_t base = (uint32_t)rowN * 128u, mask = (uint32_t)(rowN & 7) << 4;
#pragma unroll
        for (int ks = 0; ks < 4; ks++)
            fo.b[p * 4 + ks] = base + (((uint32_t)ks * 32u + lk) ^ mask);
    }
}
__device__ __forceinline__ void mm_issue(const MMCtx& cx, const __half* const* b_src,
                                         uint32_t sb, int buf, int c) {
    uint32_t ab = sb + buf * STG, bb = ab + TLB;
#pragma unroll
    for (int i = 0; i < 4; i++) cp16z(ab + cx.dst[i], cx.a_src[i] + c * KC, cx.a_sz[i]);
#pragma unroll
    for (int i = 0; i < 4; i++) cp16(bb + cx.dst[i], b_src[i] + c * KC);
    cp_commit();
}
__device__ __forceinline__ void mm_compute(uint32_t ab, uint32_t bb, const FragOff& fo,
                                           float acc[2][8][4]) {
#pragma unroll
    for (int ks = 0; ks < 4; ks++) {
        uint32_t a[2][4];
#pragma unroll
        for (int mi = 0; mi < 2; mi++)
            ldsm4(a[mi], ab + fo.a[mi * 4 + ks]);
#pragma unroll
        for (int p = 0; p < 4; p++) {
            uint32_t bf[4];
            ldsm4(bf, bb + fo.b[p * 4 + ks]);
            mma16(acc[0][2*p],   a[0], bf[0], bf[2]);
            mma16(acc[1][2*p],   a[1], bf[0], bf[2]);
            mma16(acc[0][2*p+1], a[0], bf[1], bf[3]);
            mma16(acc[1][2*p+1], a[1], bf[1], bf[3]);
        }
    }
}
__device__ __forceinline__ void mm_loop2(const MMCtx& cx, const __half* const* b_src,
                                         uint32_t sb, int K, const FragOff& fo,
                                         float acc[2][8][4]) {
    int NCH = K / KC;
    mm_issue(cx, b_src, sb, 0, 0);
    for (int c = 0; c < NCH; c++) {
        int b = c & 1;
        if (c + 1 < NCH) { mm_issue(cx, b_src, sb, b ^ 1, c + 1); cp_wait1(); }
        else             { cp_wait0(); }
        __syncthreads();
        mm_compute(sb + b * STG, sb + b * STG + TLB, fo, acc);
        __syncthreads();
    }
}
__device__ __forceinline__ void mm_loop3(const MMCtx& cx, const __half* const* b_src,
                                         uint32_t sb, int K, const FragOff& fo,
                                         float acc[2][8][4]) {
    int NCH = K / KC;
    mm_issue(cx, b_src, sb, 0, 0);
    mm_issue(cx, b_src, sb, 1, 1);
    int b = 0, b2 = 2;
    for (int c = 0; c < NCH; c++) {
        if (c == NCH - 1) cp_wait0(); else cp_wait1();
        __syncthreads();
        if (c + 2 < NCH) mm_issue(cx, b_src, sb, b2, c + 2);
        mm_compute(sb + b * STG, sb + b * STG + TLB, fo, acc);
        if (++b == 3) b = 0;
        if (++b2 == 3) b2 = 0;
    }
}

// ---------------- small kernels -------------------------------------------------
__global__ void k_zero() { if (threadIdx.x < NE) g_cnt[threadIdx.x] = 0; }

__global__ void k_half(const float* __restrict__ s, __half* __restrict__ d, int n4) {
    int i = blockIdx.x * blockDim.x + threadIdx.x;
    if (i < n4) {
        float4 v = ((const float4*)s)[i];
        __half2* o = (__half2*)d + i * 2;
        o[0] = __floats2half2_rn(v.x, v.y);
        o[1] = __floats2half2_rn(v.z, v.w);
    }
}

__global__ void k_gate(const float* __restrict__ emb, const float* __restrict__ gw)
{
    int t = (blockIdx.x * blockDim.x + threadIdx.x) >> 5;
    int lane = threadIdx.x & 31;
    if (t >= TOK) return;
    const float* row = emb + (size_t)t * DIM;
    float xr[32];
#pragma unroll
    for (int i = 0; i < 32; i++) xr[i] = row[lane + 32 * i];
    __half* eh = g_embh + (size_t)t * DIM;
#pragma unroll
    for (int i = 0; i < 32; i++) eh[lane + 32 * i] = __float2half_rn(xr[i]);
    float sc[NE];
#pragma unroll
    for (int e = 0; e < NE; e++) {
        const float* g = gw + e * DIM;
        float acc = 0.f;
#pragma unroll
        for (int i = 0; i < 32; i++) acc += xr[i] * g[lane + 32 * i];
#pragma unroll
        for (int o = 16; o > 0; o >>= 1) acc += __shfl_xor_sync(0xffffffffu, acc, o);
        sc[e] = acc;
    }
    if (lane == 0) {
        float m = sc[0];
#pragma unroll
        for (int e = 1; e < NE; e++) m = fmaxf(m, sc[e]);
        float s = 0.f;
#pragma unroll
        for (int e = 0; e < NE; e++) { sc[e] = expf(sc[e] - m); s += sc[e]; }
        float inv = 1.f / s;
        int i0 = 0;
#pragma unroll
        for (int e = 1; e < NE; e++) if (sc[e] > sc[i0]) i0 = e;
        int i1 = (i0 == 0) ? 1 : 0;
#pragma unroll
        for (int e = 0; e < NE; e++) if (e != i0 && sc[e] > sc[i1]) i1 = e;
        int p0 = atomicAdd(&g_cnt[i0], 1);
        g_list[i0 * TOK + p0] = t * 2;
        g_went[t * 2] = sc[i0] * inv;
        int p1 = atomicAdd(&g_cnt[i1], 1);
        g_list[i1 * TOK + p1] = t * 2 + 1;
        g_went[t * 2 + 1] = sc[i1] * inv;
    }
}

__global__ void k_trh(const float* __restrict__ src, __half* __restrict__ dst, int R, int C)
{
    __shared__ float t[32][33];
    int c0 = blockIdx.x * 32, r0 = blockIdx.y * 32;
    int tx = threadIdx.x, ty = threadIdx.y;
#pragma unroll
    for (int i = 0; i < 32; i += 8)
        t[ty + i][tx] = src[(size_t)(r0 + ty + i) * C + c0 + tx];
    __syncthreads();
#pragma unroll
    for (int i = 0; i < 32; i += 8)
        dst[(size_t)(c0 + ty + i) * R + r0 + tx] = __float2half_rn(t[tx][ty + i]);
}
__global__ void k_trw(const float* __restrict__ W1, __half* __restrict__ T1,
                      const float* __restrict__ W3, __half* __restrict__ T3,
                      const float* __restrict__ W2, __half* __restrict__ T2)
{
    __shared__ float t[32][33];
    int set = blockIdx.z >> 4, e = blockIdx.z & 15;
    const float* src = (set == 0) ? W1 : (set == 1) ? W3 : W2;
    __half*      dst = (set == 0) ? T1 : (set == 1) ? T3 : T2;
    size_t boff = (size_t)e * DIM * HID;
    int c0 = blockIdx.x * 32, r0 = blockIdx.y * 32;
    int tx = threadIdx.x, ty = threadIdx.y;
#pragma unroll
    for (int i = 0; i < 32; i += 8)
        t[ty + i][tx] = src[boff + (size_t)(r0 + ty + i) * HID + c0 + tx];
    __syncthreads();
#pragma unroll
    for (int i = 0; i < 32; i += 8)
        dst[boff + (size_t)(c0 + ty + i) * DIM + r0 + tx] = __float2half_rn(t[tx][ty + i]);
}

// ---------------- dense GEMM (shared expert) ------------------------------------
// EPI 0: C = acc + bias (f32)   EPI 1: g_zbufh = half(silu(acc + bias))
template<int EPI>
__global__ void __launch_bounds__(256, 2) k_dense(
    const __half* __restrict__ A, int lda,
    const __half* __restrict__ Bt, int K,
    const float* __restrict__ bias,
    float* __restrict__ C, int ldc)
{
    extern __shared__ char dsm[];
    char* base = (char*)(((uintptr_t)dsm + 127) & ~(uintptr_t)127);
    uint32_t sb = smem_u32(base);
    int tid = threadIdx.x, lane = tid & 31, w = tid >> 5;
    int wm = w & 3, wn = w >> 2;
    int r0 = blockIdx.y * BMT, c0 = blockIdx.x * BNT;

    MMCtx cx;
    const __half* bsrc[4];
    mm_setup_dst(cx, tid);
    {
        int c8 = tid & 7, rb = tid >> 3;
#pragma unroll
        for (int i = 0; i < 4; i++) {
            int row = rb + 32 * i;
            cx.a_src[i] = A + (size_t)(r0 + row) * lda + c8 * 8;
            cx.a_sz[i] = 16;
            bsrc[i] = Bt + (size_t)(c0 + row) * K + c8 * 8;
        }
    }
    FragOff fo;
    frag_setup(fo, lane, wm, wn);
    float acc[2][8][4] = {};
    mm_loop3(cx, bsrc, sb, K, fo, acc);

    int g = lane >> 2, t4 = lane & 3;
#pragma unroll
    for (int mi = 0; mi < 2; mi++)
#pragma unroll
        for (int h = 0; h < 2; h++) {
            int row = r0 + wm * 32 + mi * 16 + g + h * 8;
#pragma unroll
            for (int nj = 0; nj < 8; nj++) {
                int col = c0 + wn * 64 + nj * 8 + 2 * t4;
                float v0 = acc[mi][nj][h * 2 + 0] + bias[col];
                float v1 = acc[mi][nj][h * 2 + 1] + bias[col + 1];
                if (EPI == 1) {
                    v0 = v0 / (1.f + __expf(-v0));
                    v1 = v1 / (1.f + __expf(-v1));
                    *(__half2*)(g_zbufh + (size_t)row * SHH + col) = __floats2half2_rn(v0, v1);
                } else {
                    *(float2*)(C + (size_t)row * ldc + col) = make_float2(v0, v1);
                }
            }
        }
}

// ---------------- fused routed GEMM1: u = A@W1+b1 (pass1, smem), h = silu(u)*(A@W3+b3)
__global__ void __launch_bounds__(256, 2) k_moe13(
    const __half* __restrict__ xh, const __half* __restrict__ embh,
    const __half* __restrict__ W1t, const __half* __restrict__ W3t,
    const float* __restrict__ b1all, const float* __restrict__ b3all)
{
    int e = blockIdx.z;
    int cnt = g_cnt[e];
    int r0 = blockIdx.y * BMT;
    if (r0 >= cnt) return;
    int c0 = blockIdx.x * BNT;

    extern __shared__ char dsm[];
    __shared__ int rs[BMT];
    char* base = (char*)(((uintptr_t)dsm + 127) & ~(uintptr_t)127);
    uint32_t sb = smem_u32(base);
    uint32_t su = sb + 2 * STG;
    int tid = threadIdx.x, lane = tid & 31, w = tid >> 5;
    int wm = w & 3, wn = w >> 2;

    if (tid < BMT) rs[tid] = (r0 + tid < cnt) ? g_list[e * TOK + r0 + tid] : -1;
    __syncthreads();

    MMCtx cx;
    const __half* b1src[4];
    const __half* b3src[4];
    mm_setup_dst(cx, tid);
    {
        int c8 = tid & 7, rb = tid >> 3;
        const __half* abase = (e < 2) ? xh : embh;
#pragma unroll
        for (int i = 0; i < 4; i++) {
            int row = rb + 32 * i;
            int ent = rs[row];
            bool v = (ent >= 0);
            cx.a_src[i] = v ? abase + (size_t)(ent >> 1) * DIM + c8 * 8 : abase;
            cx.a_sz[i] = v ? 16 : 0;
            b1src[i] = W1t + ((size_t)e * HID + c0 + row) * DIM + c8 * 8;
            b3src[i] = W3t + ((size_t)e * HID + c0 + row) * DIM + c8 * 8;
        }
    }
    const float* b1 = b1all + (size_t)e * HID;
    const float* b3 = b3all + (size_t)e * HID;
    FragOff fo;
    frag_setup(fo, lane, wm, wn);
    int g = lane >> 2, t4 = lane & 3;

    float acc[2][8][4] = {};
    mm_loop2(cx, b1src, sb, DIM, fo, acc);
#pragma unroll
    for (int mi = 0; mi < 2; mi++)
#pragma unroll
        for (int h = 0; h < 2; h++)
#pragma unroll
            for (int nj = 0; nj < 8; nj++) {
                int col = c0 + wn * 64 + nj * 8 + 2 * t4;
                float u0 = acc[mi][nj][h * 2 + 0] + b1[col];
                float u1 = acc[mi][nj][h * 2 + 1] + b1[col + 1];
                int i = (mi * 2 + h) * 8 + nj;
                uint32_t ua = su + (uint32_t)i * 1024u + (uint32_t)tid * 4u;
                __half2 hu = __floats2half2_rn(u0, u1);
                asm volatile("st.shared.b32 [%0], %1;" :: "r"(ua), "r"(*(uint32_t*)&hu));
                acc[mi][nj][h * 2 + 0] = 0.f;
                acc[mi][nj][h * 2 + 1] = 0.f;
            }
    __syncthreads();

    mm_loop2(cx, b3src, sb, DIM, fo, acc);
#pragma unroll
    for (int mi = 0; mi < 2; mi++)
#pragma unroll
        for (int h = 0; h < 2; h++) {
            int lr = wm * 32 + mi * 16 + g + h * 8;
            int ent = rs[lr];
            if (ent < 0) continue;
#pragma unroll
            for (int nj = 0; nj < 8; nj++) {
                int col = c0 + wn * 64 + nj * 8 + 2 * t4;
                float v0 = acc[mi][nj][h * 2 + 0] + b3[col];
                float v1 = acc[mi][nj][h * 2 + 1] + b3[col + 1];
                int i = (mi * 2 + h) * 8 + nj;
                uint32_t ua = su + (uint32_t)i * 1024u + (uint32_t)tid * 4u;
                uint32_t ur;
                asm volatile("ld.shared.b32 %0, [%1];" : "=r"(ur) : "r"(ua));
                __half2 hu = *(__half2*)&ur;
                float u0 = __half2float(__low2half(hu));
                float u1 = __half2float(__high2half(hu));
                v0 = (u0 / (1.f + __expf(-u0))) * v0;
                v1 = (u1 / (1.f + __expf(-u1))) * v1;
                *(__half2*)(g_hbufh + (size_t)ent * HID + col) = __floats2half2_rn(v0, v1);
            }
        }
}

// ---------------- routed GEMM2: ubuf[ent] = hbufh[ent] @ W2 + b2 (f32) ------------
__global__ void __launch_bounds__(256, 2) k_moe2(
    const __half* __restrict__ W2t,
    const float* __restrict__ b2all)
{
    int e = blockIdx.z;
    int cnt = g_cnt[e];
    int r0 = blockIdx.y * BMT;
    if (r0 >= cnt) return;
    int c0 = blockIdx.x * BNT;

    extern __shared__ char dsm[];
    __shared__ int rs[BMT];
    char* base = (char*)(((uintptr_t)dsm + 127) & ~(uintptr_t)127);
    uint32_t sb = smem_u32(base);
    int tid = threadIdx.x, lane = tid & 31, w = tid >> 5;
    int wm = w & 3, wn = w >> 2;

    if (tid < BMT) rs[tid] = (r0 + tid < cnt) ? g_list[e * TOK + r0 + tid] : -1;
    __syncthreads();

    MMCtx cx;
    const __half* bsrc[4];
    mm_setup_dst(cx, tid);
    {
        int c8 = tid & 7, rb = tid >> 3;
#pragma unroll
        for (int i = 0; i < 4; i++) {
            int row = rb + 32 * i;
            int ent = rs[row];
            bool v = (ent >= 0);
            cx.a_src[i] = v ? g_hbufh + (size_t)ent * HID + c8 * 8 : g_hbufh;
            cx.a_sz[i] = v ? 16 : 0;
            bsrc[i] = W2t + ((size_t)e * DIM + c0 + row) * HID + c8 * 8;
        }
    }
    FragOff fo;
    frag_setup(fo, lane, wm, wn);
    float acc[2][8][4] = {};
    mm_loop3(cx, bsrc, sb, HID, fo, acc);

    const float* bias = b2all + (size_t)e * DIM;
    int g = lane >> 2, t4 = lane & 3;
#pragma unroll
    for (int mi = 0; mi < 2; mi++)
#pragma unroll
        for (int h = 0; h < 2; h++) {
            int lr = wm * 32 + mi * 16 + g + h * 8;
            int ent = rs[lr];
            if (ent < 0) continue;
#pragma unroll
            for (int nj = 0; nj < 8; nj++) {
                int col = c0 + wn * 64 + nj * 8 + 2 * t4;
                float v0 = acc[mi][nj][h * 2 + 0] + bias[col];
                float v1 = acc[mi][nj][h * 2 + 1] + bias[col + 1];
                *(float2*)(g_ubuf + (size_t)ent * DIM + col) = make_float2(v0, v1);
            }
        }
}

// ---------------- final combine: out[t] += w0*o[2t] + w1*o[2t+1] ------------------
__global__ void k_comb(float* __restrict__ out) {
    int t = blockIdx.x;
    int d = threadIdx.x * 4;
    float w0 = g_went[t * 2], w1 = g_went[t * 2 + 1];
    float4 a = *(const float4*)(g_ubuf + (size_t)(t * 2) * DIM + d);
    float4 b = *(const float4*)(g_ubuf + (size_t)(t * 2 + 1) * DIM + d);
    float4 z = *(float4*)(out + (size_t)t * DIM + d);
    z.x += w0 * a.x + w1 * b.x;
    z.y += w0 * a.y + w1 * b.y;
    z.z += w0 * a.z + w1 * b.z;
    z.w += w0 * a.w + w1 * b.w;
    *(float4*)(out + (size_t)t * DIM + d) = z;
}

// ---------------- launcher ---------------------------------------------------------
extern "C" void kernel_launch(void* const* d_in, const int* in_sizes, int n_in,
                              void* d_out, int out_size)
{
    const float* emb = (const float*)d_in[0];
    const float* x   = (const float*)d_in[1];
    const float* gw  = (const float*)d_in[2];
    const float* W1  = (const float*)d_in[3];
    const float* B1  = (const float*)d_in[4];
    const float* W2  = (const float*)d_in[5];
    const float* B2  = (const float*)d_in[6];
    const float* W3  = (const float*)d_in[7];
    const float* B3  = (const float*)d_in[8];
    const float* sW1 = (const float*)d_in[9];
    const float* sB1 = (const float*)d_in[10];
    const float* sW2 = (const float*)d_in[11];
    const float* sB2 = (const float*)d_in[12];
    float* out = (float*)d_out;

    static cudaStream_t s_aux = nullptr;
    static cudaEvent_t  s_evA = nullptr, s_evB = nullptr, s_evC = nullptr, s_evD = nullptr;
    if (!s_aux) {
        cudaStreamCreateWithFlags(&s_aux, cudaStreamNonBlocking);
        cudaEventCreateWithFlags(&s_evA, cudaEventDisableTiming);
        cudaEventCreateWithFlags(&s_evB, cudaEventDisableTiming);
        cudaEventCreateWithFlags(&s_evC, cudaEventDisableTiming);
        cudaEventCreateWithFlags(&s_evD, cudaEventDisableTiming);
    }

    cudaFuncSetAttribute(k_dense<0>, cudaFuncAttributeMaxDynamicSharedMemorySize, SMEM_G3);
    cudaFuncSetAttribute(k_dense<1>, cudaFuncAttributeMaxDynamicSharedMemorySize, SMEM_G3);
    cudaFuncSetAttribute(k_moe13,    cudaFuncAttributeMaxDynamicSharedMemorySize, SMEM_FUSED);
    cudaFuncSetAttribute(k_moe2,     cudaFuncAttributeMaxDynamicSharedMemorySize, SMEM_G3);

    __half *embh, *xh, *zbufh, *tw1h, *tw3h, *tw2h, *tsw1h, *tsw2h;
    cudaGetSymbolAddress((void**)&embh,  g_embh);
    cudaGetSymbolAddress((void**)&xh,    g_xh);
    cudaGetSymbolAddress((void**)&zbufh, g_zbufh);
    cudaGetSymbolAddress((void**)&tw1h,  g_tw1h);
    cudaGetSymbolAddress((void**)&tw3h,  g_tw3h);
    cudaGetSymbolAddress((void**)&tw2h,  g_tw2h);
    cudaGetSymbolAddress((void**)&tsw1h, g_tsw1h);
    cudaGetSymbolAddress((void**)&tsw2h, g_tsw2h);

    dim3 tb(32, 8);
    int n4a = TOK * DIM / 4;

    // stream 0: zero, then fork
    k_zero<<<1, 32>>>();
    cudaEventRecord(s_evA, 0);

    // aux stream: DRAM-bound prep overlapping with gate + dense<1> on stream 0
    cudaStreamWaitEvent(s_aux, s_evA, 0);
    k_half<<<(n4a + 255) / 256, 256, 0, s_aux>>>(x, xh, n4a);
    k_trh <<<dim3(DIM / 32, SHH / 32), tb, 0, s_aux>>>(sW2, tsw2h, SHH, DIM);
    k_trw <<<dim3(HID / 32, DIM / 32, 3 * NE), tb, 0, s_aux>>>(W1, tw1h, W3, tw3h, W2, tw2h);
    cudaEventRecord(s_evB, s_aux);

    // stream 0 main branch (tensor-bound)
    k_trh<<<dim3(SHH / 32, DIM / 32), tb>>>(sW1, tsw1h, DIM, SHH);
    k_gate<<<TOK / 4, 128>>>(emb, gw);
    k_dense<1><<<dim3(SHH / BNT, TOK / BMT), 256, SMEM_G3>>>(embh, DIM, tsw1h, DIM, sB1, out, SHH);
    cudaEventRecord(s_evC, 0);

    // join for the routed path on stream 0
    cudaStreamWaitEvent(0, s_evB, 0);
    k_moe13<<<dim3(HID / BNT, TOK / BMT, NE), 256, SMEM_FUSED>>>(xh, embh, tw1h, tw3h, B1, B3);

    // dense<0> on aux, concurrent with k_moe13 (independent data)
    cudaStreamWaitEvent(s_aux, s_evC, 0);
    k_dense<0><<<dim3(DIM / BNT, TOK / BMT), 256, SMEM_G3, s_aux>>>(zbufh, SHH, tsw2h, SHH, sB2, out, DIM);
    cudaEventRecord(s_evD, s_aux);

    // moe2 follows moe13 on stream 0; comb waits for dense<0> as well
    k_moe2<<<dim3(DIM / BNT, TOK / BMT, NE), 256, SMEM_G3>>>(tw2h, B2);
    cudaStreamWaitEvent(0, s_evD, 0);
    k_comb<<<TOK, 256>>>(out);

    (void)in_sizes; (void)n_in; (void)out_size;
}